// round 4
// baseline (speedup 1.0000x reference)
#include <cuda_runtime.h>
#include <math.h>

#define NB 64
#define NS 256
#define NU 1024
#define NT 512
#define GRID 148
#define NTH 256
#define GTH (GRID * NTH)

// ------------------------- device scratch -------------------------
__device__ float g_hproj[NB * NS * NU];     // 64 MB
__device__ float g_s[NB * NU];
__device__ float g_t1[NB * NU];
__device__ float g_q[NB * NU];
__device__ float g_y[NB * NT];
__device__ float g_e[NB * NS];
__device__ float g_a[NB * NS];
__device__ float g_c[NB * NU];
__device__ float g_slab1[8 * NB * 2048];    // t1|q split-K partials
__device__ float g_slaby[8 * NB * NT];      // y partials
__device__ float g_slabg[8 * NB * 4096];    // gate partials [i|f|g|o]
__device__ float2 g_lut_sig[2049];
__device__ float2 g_lut_tanh[2049];
__device__ unsigned g_cnt;
__device__ unsigned g_phs;

// ------------------------- LUT activation (1 LDS + ~4 FMA) -------------------------
__device__ __forceinline__ float lut_eval(const float2* __restrict__ lut, float x) {
    float xc = fminf(fmaxf(x, -8.0f), 8.0f);
    float f  = fmaf(xc, 128.0f, 1024.0f);         // [0, 2048]
    float m  = (f - 0.5f) + 12582912.0f;          // floor via magic round
    int  idx = __float_as_int(m) - 0x4B400000;
    float fr = f - (m - 12582912.0f);             // frac in [0,1)
    float2 p = lut[idx];
    return fmaf(fr, p.y, p.x);
}

// ------------------------- grid barrier (all 148 CTAs resident) --------------------
__device__ __forceinline__ void gsync(unsigned& tgt) {
    tgt++;
    __syncthreads();
    if (threadIdx.x == 0) {
        __threadfence();                               // release (flush writes)
        if (atomicAdd(&g_cnt, 1u) == GRID - 1) {
            g_cnt = 0;
            __threadfence();
            atomicExch(&g_phs, tgt);
        } else {
            while (*(volatile unsigned*)&g_phs < tgt) { }
        }
    }
    __syncthreads();
    __threadfence();                                   // acquire: CCTL.IVALL (L1 inval)
}

// ------------------------- init ----------------------------------------------------
__global__ void k_init(const float* __restrict__ s0) {
    int tid = threadIdx.x;
    if (blockIdx.x == 0) {
        if (tid == 0) { g_cnt = 0; g_phs = 0; }
        for (int i = tid; i < 2049; i += NTH) {
            float x0 = -8.0f + i * (1.0f / 128.0f);
            float x1 = x0 + (1.0f / 128.0f);
            float sa = 1.0f / (1.0f + expf(-x0));
            float sb = (i == 2048) ? sa : 1.0f / (1.0f + expf(-x1));
            g_lut_sig[i] = make_float2(sa, sb - sa);
            float ta = tanhf(x0);
            float tb = (i == 2048) ? ta : tanhf(x1);
            g_lut_tanh[i] = make_float2(ta, tb - ta);
        }
    } else {
        int b = blockIdx.x - 1;
        for (int u = tid; u < NU; u += NTH) g_s[b * NU + u] = s0[b * NU + u];
    }
}

// ------------------------- GEMM: 64 x 128 tile, 256 threads ------------------------
// warp w -> rows w*8..w*8+7 ; lane l -> cols l*4..l*4+3 (conflict-free LDS.128)
struct XGlobal {
    const float* X; int ldx;
    __device__ __forceinline__ float4 ld(int r, int k) const {
        return *(const float4*)(X + (size_t)r * ldx + k);
    }
};
struct XConcatYS {   // x_h = [y (512) | s (1024)]
    __device__ __forceinline__ float4 ld(int r, int k) const {
        return (k < NT) ? *(const float4*)(g_y + (size_t)r * NT + k)
                        : *(const float4*)(g_s + (size_t)r * NU + (k - NT));
    }
};

template <typename XL>
__device__ __forceinline__ void gemm_64x128(
    const XL& xl, const float* __restrict__ W, int ldw, int wcol0,
    int k0, int nkb, float* __restrict__ Xs, float* __restrict__ Ws, float acc[8][4])
{
    const int tid = threadIdx.x;
    const int xr  = tid & 63;               // X loader row
    const int xk  = (tid >> 6) << 2;        // X loader k offset (0,4,8,12)
    const int wk  = tid >> 4;               // W loader k row (0..15)
    const int wn  = (tid & 15) << 3;        // W loader col (0..120, step 8)
    const int wr  = tid >> 5;               // compute: row group (0..7)
    const int lc  = (tid & 31) << 2;        // compute: col (lane*4)

    for (int kb = 0; kb < nkb; kb++) {
        int kg = k0 + kb * 16;
        float4 xv = xl.ld(xr, kg + xk);
        const float* wp = W + (size_t)(kg + wk) * ldw + wcol0 + wn;
        float4 wv0 = *(const float4*)wp;
        float4 wv1 = *(const float4*)(wp + 4);
        __syncthreads();
        Xs[(xk + 0) * 68 + xr] = xv.x;
        Xs[(xk + 1) * 68 + xr] = xv.y;
        Xs[(xk + 2) * 68 + xr] = xv.z;
        Xs[(xk + 3) * 68 + xr] = xv.w;
        *(float4*)(Ws + wk * 132 + wn)     = wv0;
        *(float4*)(Ws + wk * 132 + wn + 4) = wv1;
        __syncthreads();
#pragma unroll
        for (int kk = 0; kk < 16; kk++) {
            const float* xp = Xs + kk * 68 + wr * 8;
            float4 a0 = *(const float4*)xp;
            float4 a1 = *(const float4*)(xp + 4);
            float4 b  = *(const float4*)(Ws + kk * 132 + lc);
            float am[8] = {a0.x, a0.y, a0.z, a0.w, a1.x, a1.y, a1.z, a1.w};
#pragma unroll
            for (int i = 0; i < 8; i++) {
                acc[i][0] = fmaf(am[i], b.x, acc[i][0]);
                acc[i][1] = fmaf(am[i], b.y, acc[i][1]);
                acc[i][2] = fmaf(am[i], b.z, acc[i][2]);
                acc[i][3] = fmaf(am[i], b.w, acc[i][3]);
            }
        }
    }
}

// ------------------------- h_proj = h @ We1_h (normal grid kernel) -----------------
__global__ __launch_bounds__(NTH) void k_hproj(const float* __restrict__ h,
                                               const float* __restrict__ We1) {
    __shared__ float sbuf[16 * 68 + 16 * 132];
    float acc[8][4] = {};
    int mt = blockIdx.x >> 3, nt = blockIdx.x & 7;
    XGlobal xl{h + (size_t)mt * 64 * NU, NU};
    gemm_64x128(xl, We1, NU, nt * 128, 0, 64, sbuf, sbuf + 1088, acc);
    int wr = threadIdx.x >> 5, lc = (threadIdx.x & 31) << 2;
#pragma unroll
    for (int i = 0; i < 8; i++)
        *(float4*)(g_hproj + ((size_t)mt * 64 + wr * 8 + i) * NU + nt * 128 + lc) =
            make_float4(acc[i][0], acc[i][1], acc[i][2], acc[i][3]);
}

// ------------------------- persistent scan kernel ----------------------------------
__global__ __launch_bounds__(NTH) void k_persist(
    const float* __restrict__ h,
    const float* __restrict__ Wy1, const float* __restrict__ by1,
    const float* __restrict__ Wy2, const float* __restrict__ by2,
    const float* __restrict__ We1, const float* __restrict__ be1,
    const float* __restrict__ We2, const float* __restrict__ be2,
    const float* __restrict__ Wi,  const float* __restrict__ bi,
    const float* __restrict__ Wf,  const float* __restrict__ bf,
    const float* __restrict__ Wg,  const float* __restrict__ bg,
    const float* __restrict__ Wo,  const float* __restrict__ bo,
    float* __restrict__ out)
{
    __shared__ float2 lsig[2049], ltanh[2049];
    __shared__ float  sbuf[16 * 68 + 16 * 132];   // 3200 floats, reused per phase
    const int tid = threadIdx.x;
    const int bid = blockIdx.x;
    const int gid = bid * NTH + tid;
    const int wr  = tid >> 5, lc = (tid & 31) << 2;
    const int warp = tid >> 5, lane = tid & 31;

    for (int i = tid; i < 2049; i += NTH) { lsig[i] = g_lut_sig[i]; ltanh[i] = g_lut_tanh[i]; }
    __syncthreads();
    const float be2v = be2[0];
    unsigned tgt = 0;

    for (int t = 0; t < NS; t++) {
        // ---- P1: t1|q split-K GEMM: 16 tiles x 8 k-slices ----
        for (int j = bid; j < 128; j += GRID) {
            int nt = j >> 3, ks = j & 7, col0 = nt * 128;
            const float* W; int wc;
            if (col0 < NU) { W = Wy1; wc = col0; }
            else           { W = We1 + (size_t)NU * NU; wc = col0 - NU; }
            float acc[8][4] = {};
            XGlobal xl{g_s, NU};
            gemm_64x128(xl, W, NU, wc, ks * 128, 8, sbuf, sbuf + 1088, acc);
#pragma unroll
            for (int i = 0; i < 8; i++)
                *(float4*)(g_slab1 + ((size_t)(ks * NB + wr * 8 + i)) * 2048 + col0 + lc) =
                    make_float4(acc[i][0], acc[i][1], acc[i][2], acc[i][3]);
        }
        gsync(tgt);

        // ---- P2: reduce slabs -> t1 (tanh), q ----
        for (int idx = gid; idx < NB * 2048; idx += GTH) {
            int row = idx >> 11, col = idx & 2047;
            float s = 0.f;
#pragma unroll
            for (int ks = 0; ks < 8; ks++) s += g_slab1[(size_t)(ks * NB + row) * 2048 + col];
            if (col < NU) g_t1[row * NU + col] = lut_eval(ltanh, s + by1[col]);
            else          g_q[row * NU + (col - NU)] = s + be1[col - NU];
        }
        gsync(tgt);

        // ---- P3: y split-K GEMM (32 jobs) + energies (2048 jobs) ----
        for (int j = bid; j < 32 + 2048; j += GRID) {
            if (j < 32) {
                int nt = j >> 3, ks = j & 7, col0 = nt * 128;
                float acc[8][4] = {};
                XGlobal xl{g_t1, NU};
                gemm_64x128(xl, Wy2, NT, col0, ks * 128, 8, sbuf, sbuf + 1088, acc);
#pragma unroll
                for (int i = 0; i < 8; i++)
                    *(float4*)(g_slaby + ((size_t)(ks * NB + wr * 8 + i)) * NT + col0 + lc) =
                        make_float4(acc[i][0], acc[i][1], acc[i][2], acc[i][3]);
            } else {
                int e = j - 32, b = e >> 5, sg = e & 31;
                __syncthreads();
                for (int i = tid; i < NU; i += NTH) {
                    sbuf[i]      = g_q[b * NU + i];
                    sbuf[NU + i] = We2[i];
                }
                __syncthreads();
                int s = sg * 8 + warp;
                const float* hp = g_hproj + ((size_t)(b * NS + s)) * NU;
                float av = 0.f;
#pragma unroll
                for (int i2 = 0; i2 < 8; i2++) {
                    int u = i2 * 128 + lane * 4;
                    float4 hv = *(const float4*)(hp + u);
                    float4 qv = *(const float4*)(sbuf + u);
                    float4 wv = *(const float4*)(sbuf + NU + u);
                    av = fmaf(lut_eval(lsig, hv.x + qv.x), wv.x, av);
                    av = fmaf(lut_eval(lsig, hv.y + qv.y), wv.y, av);
                    av = fmaf(lut_eval(lsig, hv.z + qv.z), wv.z, av);
                    av = fmaf(lut_eval(lsig, hv.w + qv.w), wv.w, av);
                }
#pragma unroll
                for (int o = 16; o > 0; o >>= 1) av += __shfl_down_sync(0xffffffffu, av, o);
                if (lane == 0) g_e[b * NS + s] = lut_eval(lsig, av + be2v);
            }
        }
        gsync(tgt);

        // ---- P4: y reduce + bias + out write; softmax -> alpha ----
        for (int idx = gid; idx < NB * NT; idx += GTH) {
            int row = idx >> 9, col = idx & 511;
            float s = 0.f;
#pragma unroll
            for (int ks = 0; ks < 8; ks++) s += g_slaby[(size_t)(ks * NB + row) * NT + col];
            float v = s + by2[col];
            g_y[row * NT + col] = v;
            out[((size_t)row * NS + t) * NT + col] = v;
        }
        if (bid < NB) {
            int b = bid;
            float ev = g_e[b * NS + tid];
            __syncthreads();
            sbuf[tid] = ev;
            __syncthreads();
            for (int o = 128; o > 0; o >>= 1) {
                if (tid < o) sbuf[tid] = fmaxf(sbuf[tid], sbuf[tid + o]);
                __syncthreads();
            }
            float mx = sbuf[0];
            __syncthreads();
            float p = expf(ev - mx);
            sbuf[tid] = p;
            __syncthreads();
            for (int o = 128; o > 0; o >>= 1) {
                if (tid < o) sbuf[tid] += sbuf[tid + o];
                __syncthreads();
            }
            g_a[b * NS + tid] = p * (1.0f / sbuf[0]);
        }
        gsync(tgt);

        // ---- P5: gates split-K GEMM (256 jobs) + context (256 jobs) ----
        for (int j = bid; j < 512; j += GRID) {
            if (j < 256) {
                int nt = j >> 3, ks = j & 7;
                int gate = nt >> 3, gc0 = (nt & 7) * 128;
                const float* W = (gate == 0) ? Wi : (gate == 1) ? Wf : (gate == 2) ? Wg : Wo;
                float acc[8][4] = {};
                XConcatYS xl;
                gemm_64x128(xl, W, NU, gc0, ks * 192, 12, sbuf, sbuf + 1088, acc);
#pragma unroll
                for (int i = 0; i < 8; i++)
                    *(float4*)(g_slabg + ((size_t)(ks * NB + wr * 8 + i)) * 4096 +
                               gate * NU + gc0 + lc) =
                        make_float4(acc[i][0], acc[i][1], acc[i][2], acc[i][3]);
            } else {
                int cj = j - 256, b = cj >> 2, u0 = (cj & 3) * 256;
                __syncthreads();
                sbuf[tid] = g_a[b * NS + tid];
                __syncthreads();
                int u = u0 + tid;
                const float* hb = h + (size_t)b * NS * NU + u;
                float av = 0.f;
#pragma unroll 16
                for (int s2 = 0; s2 < NS; s2++)
                    av = fmaf(hb[(size_t)s2 * NU], sbuf[s2], av);
                g_c[b * NU + u] = av;
            }
        }
        gsync(tgt);

        // ---- P6: reduce gates + activations + s' = o*tanh(f*c + i*g) ----
        for (int idx = gid; idx < NB * NU; idx += GTH) {
            int b = idx >> 10, u = idx & 1023;
            float iv = bi[u], fv = bf[u], gv = bg[u], ov = bo[u];
#pragma unroll
            for (int ks = 0; ks < 8; ks++) {
                const float* p = g_slabg + (size_t)(ks * NB + b) * 4096 + u;
                iv += p[0];
                fv += p[NU];
                gv += p[2 * NU];
                ov += p[3 * NU];
            }
            iv = lut_eval(lsig, iv);
            fv = lut_eval(lsig, fv);
            gv = lut_eval(ltanh, gv);
            ov = lut_eval(lsig, ov);
            float cn = fmaf(fv, g_c[idx], iv * gv);
            g_s[idx] = ov * lut_eval(ltanh, cn);
        }
        gsync(tgt);
    }
}

// ------------------------- launch --------------------------------------------------
extern "C" void kernel_launch(void* const* d_in, const int* in_sizes, int n_in,
                              void* d_out, int out_size) {
    (void)in_sizes; (void)n_in; (void)out_size;
    const float* h   = (const float*)d_in[0];
    const float* s0  = (const float*)d_in[1];
    const float* Wy1 = (const float*)d_in[2];
    const float* by1 = (const float*)d_in[3];
    const float* Wy2 = (const float*)d_in[4];
    const float* by2 = (const float*)d_in[5];
    const float* We1 = (const float*)d_in[6];
    const float* be1 = (const float*)d_in[7];
    const float* We2 = (const float*)d_in[8];
    const float* be2 = (const float*)d_in[9];
    const float* Wf  = (const float*)d_in[10];
    const float* bf  = (const float*)d_in[11];
    const float* Wi  = (const float*)d_in[12];
    const float* bi  = (const float*)d_in[13];
    const float* Wg  = (const float*)d_in[14];
    const float* bg  = (const float*)d_in[15];
    const float* Wo  = (const float*)d_in[16];
    const float* bo  = (const float*)d_in[17];
    float* out = (float*)d_out;

    k_init<<<65, NTH>>>(s0);
    k_hproj<<<2048, NTH>>>(h, We1);
    k_persist<<<GRID, NTH>>>(h, Wy1, by1, Wy2, by2, We1, be1, We2, be2,
                             Wi, bi, Wf, bf, Wg, bg, Wo, bo, out);
}

// round 5
// speedup vs baseline: 1.1412x; 1.1412x over previous
#include <cuda_runtime.h>
#include <cuda_bf16.h>
#include <math.h>

#define NB 64
#define NS 256
#define NU 1024
#define NT 512
#define NTH 256

// ------------------------- device scratch -------------------------
__device__ __nv_bfloat16 g_hprojb[NB * NS * NU];  // 32 MB, bf16
__device__ float g_s[NB * NU];
__device__ float g_t1[NB * NU];
__device__ float g_q[NB * NU];
__device__ float g_y[NB * NT];
__device__ float g_e[NB * NS];
__device__ float g_a[NB * NS];
__device__ float g_c[NB * NU];
__device__ float g_slab1[8 * NB * 2048];          // t1|q split-K partials (8 slices)
__device__ float g_slaby[16 * NB * NT];           // y partials (16 slices)
__device__ float g_slabg[16 * NB * 4096];         // gate partials (16 slices)
__device__ float2 g_lut_sig[2049];
__device__ float2 g_lut_tanh[2049];
__device__ unsigned g_cnt;
__device__ unsigned g_phs;
__device__ unsigned g_tick[512];                  // dynamic-phase ticket counters

// ------------------------- LUT activation (1 LDS + ~4 FMA) -------------------------
__device__ __forceinline__ float lut_eval(const float2* __restrict__ lut, float x) {
    float xc = fminf(fmaxf(x, -8.0f), 8.0f);
    float f  = fmaf(xc, 128.0f, 1024.0f);         // [0, 2048]
    float m  = (f - 0.5f) + 12582912.0f;          // floor via magic round
    int  idx = __float_as_int(m) - 0x4B400000;
    float fr = f - (m - 12582912.0f);             // frac in [0,1)
    float2 p = lut[idx];
    return fmaf(fr, p.y, p.x);
}

// ------------------------- grid barrier (thread-0 fences only) ---------------------
__device__ __forceinline__ void gsync(unsigned& tgt) {
    tgt++;
    __syncthreads();
    if (threadIdx.x == 0) {
        __threadfence();                                   // release
        if (atomicAdd(&g_cnt, 1u) == gridDim.x - 1) {
            g_cnt = 0;
            __threadfence();
            atomicExch(&g_phs, tgt);
        } else {
            while (*(volatile unsigned*)&g_phs < tgt) { }
        }
        __threadfence();                                   // acquire: IVALL (SM-wide)
    }
    __syncthreads();
}

// ------------------------- init ----------------------------------------------------
__global__ void k_init(const float* __restrict__ s0) {
    int tid = threadIdx.x;
    if (blockIdx.x == 0) {
        if (tid == 0) { g_cnt = 0; g_phs = 0; }
        for (int i = tid; i < 512; i += NTH) g_tick[i] = 0;
        for (int i = tid; i < 2049; i += NTH) {
            float x0 = -8.0f + i * (1.0f / 128.0f);
            float x1 = x0 + (1.0f / 128.0f);
            float sa = 1.0f / (1.0f + expf(-x0));
            float sb = (i == 2048) ? sa : 1.0f / (1.0f + expf(-x1));
            g_lut_sig[i] = make_float2(sa, sb - sa);
            float ta = tanhf(x0);
            float tb = (i == 2048) ? ta : tanhf(x1);
            g_lut_tanh[i] = make_float2(ta, tb - ta);
        }
    } else {
        int b = blockIdx.x - 1;
        for (int u = tid; u < NU; u += NTH) g_s[b * NU + u] = s0[b * NU + u];
    }
}

// ------------------------- GEMM: 64 x 128 tile, 256 threads ------------------------
struct XGlobal {
    const float* X; int ldx;
    __device__ __forceinline__ float4 ld(int r, int k) const {
        return *(const float4*)(X + (size_t)r * ldx + k);
    }
};
struct XConcatYS {   // x_h = [y (512) | s (1024)]
    __device__ __forceinline__ float4 ld(int r, int k) const {
        return (k < NT) ? *(const float4*)(g_y + (size_t)r * NT + k)
                        : *(const float4*)(g_s + (size_t)r * NU + (k - NT));
    }
};

template <typename XL>
__device__ __forceinline__ void gemm_64x128(
    const XL& xl, const float* __restrict__ W, int ldw, int wcol0,
    int k0, int nkb, float* __restrict__ Xs, float* __restrict__ Ws, float acc[8][4])
{
    const int tid = threadIdx.x;
    const int xr  = tid & 63;
    const int xk  = (tid >> 6) << 2;
    const int wk  = tid >> 4;
    const int wn  = (tid & 15) << 3;
    const int wr  = tid >> 5;
    const int lc  = (tid & 31) << 2;

    for (int kb = 0; kb < nkb; kb++) {
        int kg = k0 + kb * 16;
        float4 xv = xl.ld(xr, kg + xk);
        const float* wp = W + (size_t)(kg + wk) * ldw + wcol0 + wn;
        float4 wv0 = *(const float4*)wp;
        float4 wv1 = *(const float4*)(wp + 4);
        __syncthreads();
        Xs[(xk + 0) * 68 + xr] = xv.x;
        Xs[(xk + 1) * 68 + xr] = xv.y;
        Xs[(xk + 2) * 68 + xr] = xv.z;
        Xs[(xk + 3) * 68 + xr] = xv.w;
        *(float4*)(Ws + wk * 132 + wn)     = wv0;
        *(float4*)(Ws + wk * 132 + wn + 4) = wv1;
        __syncthreads();
#pragma unroll
        for (int kk = 0; kk < 16; kk++) {
            const float* xp = Xs + kk * 68 + wr * 8;
            float4 a0 = *(const float4*)xp;
            float4 a1 = *(const float4*)(xp + 4);
            float4 b  = *(const float4*)(Ws + kk * 132 + lc);
            float am[8] = {a0.x, a0.y, a0.z, a0.w, a1.x, a1.y, a1.z, a1.w};
#pragma unroll
            for (int i = 0; i < 8; i++) {
                acc[i][0] = fmaf(am[i], b.x, acc[i][0]);
                acc[i][1] = fmaf(am[i], b.y, acc[i][1]);
                acc[i][2] = fmaf(am[i], b.z, acc[i][2]);
                acc[i][3] = fmaf(am[i], b.w, acc[i][3]);
            }
        }
    }
}

// ------------------------- h_proj = h @ We1_h -> bf16 (once) -----------------------
__global__ __launch_bounds__(NTH) void k_hproj(const float* __restrict__ h,
                                               const float* __restrict__ We1) {
    __shared__ float sbuf[16 * 68 + 16 * 132];
    float acc[8][4] = {};
    int mt = blockIdx.x >> 3, nt = blockIdx.x & 7;
    XGlobal xl{h + (size_t)mt * 64 * NU, NU};
    gemm_64x128(xl, We1, NU, nt * 128, 0, 64, sbuf, sbuf + 1088, acc);
    int wr = threadIdx.x >> 5, lc = (threadIdx.x & 31) << 2;
#pragma unroll
    for (int i = 0; i < 8; i++) {
        __nv_bfloat162 p0 = __floats2bfloat162_rn(acc[i][0], acc[i][1]);
        __nv_bfloat162 p1 = __floats2bfloat162_rn(acc[i][2], acc[i][3]);
        size_t off = ((size_t)mt * 64 + wr * 8 + i) * NU + nt * 128 + lc;
        *(__nv_bfloat162*)(g_hprojb + off)     = p0;
        *(__nv_bfloat162*)(g_hprojb + off + 2) = p1;
    }
}

// ------------------------- persistent scan kernel ----------------------------------
__global__ __launch_bounds__(NTH) void k_persist(
    const float* __restrict__ h,
    const float* __restrict__ Wy1, const float* __restrict__ by1,
    const float* __restrict__ Wy2, const float* __restrict__ by2,
    const float* __restrict__ We1, const float* __restrict__ be1,
    const float* __restrict__ We2, const float* __restrict__ be2,
    const float* __restrict__ Wi,  const float* __restrict__ bi,
    const float* __restrict__ Wf,  const float* __restrict__ bf,
    const float* __restrict__ Wg,  const float* __restrict__ bg,
    const float* __restrict__ Wo,  const float* __restrict__ bo,
    float* __restrict__ out)
{
    __shared__ float2 lsig[2049], ltanh[2049];
    __shared__ float  sbuf[16 * 68 + 16 * 132];
    __shared__ int    s_job;
    const int tid  = threadIdx.x;
    const int bid  = blockIdx.x;
    const int gth  = gridDim.x * NTH;
    const int gid  = bid * NTH + tid;
    const int wr   = tid >> 5, lc = (tid & 31) << 2;
    const int warp = tid >> 5, lane = tid & 31;

    for (int i = tid; i < 2049; i += NTH) { lsig[i] = g_lut_sig[i]; ltanh[i] = g_lut_tanh[i]; }
    __syncthreads();
    const float be2v = be2[0];
    unsigned tgt = 0;

    for (int t = 0; t < NS; t++) {
        // ==== P1 (static, 128 uniform jobs): t1|q split-K GEMM, 8 k-slices ====
        for (int j = bid; j < 128; j += gridDim.x) {
            int nt = j >> 3, ks = j & 7, col0 = nt * 128;
            const float* W; int wc;
            if (col0 < NU) { W = Wy1; wc = col0; }
            else           { W = We1 + (size_t)NU * NU; wc = col0 - NU; }
            float acc[8][4] = {};
            XGlobal xl{g_s, NU};
            gemm_64x128(xl, W, NU, wc, ks * 128, 8, sbuf, sbuf + 1088, acc);
#pragma unroll
            for (int i = 0; i < 8; i++)
                *(float4*)(g_slab1 + ((size_t)(ks * NB + wr * 8 + i)) * 2048 + col0 + lc) =
                    make_float4(acc[i][0], acc[i][1], acc[i][2], acc[i][3]);
        }
        gsync(tgt);

        // ==== P2 (static elementwise): reduce -> t1 (tanh), q ====
        for (int idx = gid; idx < NB * 2048; idx += gth) {
            int row = idx >> 11, col = idx & 2047;
            float s = 0.f;
#pragma unroll
            for (int ks = 0; ks < 8; ks++) s += g_slab1[(size_t)(ks * NB + row) * 2048 + col];
            if (col < NU) g_t1[row * NU + col] = lut_eval(ltanh, s + by1[col]);
            else          g_q[row * NU + (col - NU)] = s + be1[col - NU];
        }
        gsync(tgt);

        // ==== P3 (dynamic): 64 y-GEMM jobs then 512 energy jobs ====
        {
            const int NJ = 64 + 512;
            unsigned* tick = &g_tick[2 * t];
            if (tid == 0) s_job = atomicAdd(tick, 1u);
            __syncthreads();
            int job = s_job;
            while (job < NJ) {
                int nxt = 0;
                if (tid == 0) nxt = atomicAdd(tick, 1u);
                if (job < 64) {
                    int nt = job & 3, ks = job >> 2, col0 = nt * 128;
                    float acc[8][4] = {};
                    XGlobal xl{g_t1, NU};
                    gemm_64x128(xl, Wy2, NT, col0, ks * 64, 4, sbuf, sbuf + 1088, acc);
#pragma unroll
                    for (int i = 0; i < 8; i++)
                        *(float4*)(g_slaby + ((size_t)(ks * NB + wr * 8 + i)) * NT + col0 + lc) =
                            make_float4(acc[i][0], acc[i][1], acc[i][2], acc[i][3]);
                } else {
                    int e = job - 64, b = e >> 3, sg = e & 7;
                    float4* sQW = (float4*)sbuf;
                    const float2* qp = (const float2*)(g_q + (size_t)b * NU);
                    const float2* wp = (const float2*)We2;
                    for (int i = tid; i < 512; i += NTH) {
                        float2 qa = qp[i]; float2 wa = wp[i];
                        sQW[i] = make_float4(qa.x, qa.y, wa.x, wa.y);
                    }
                    __syncthreads();
#pragma unroll
                    for (int r = 0; r < 4; r++) {
                        int s = sg * 32 + warp * 4 + r;
                        const unsigned* hp = (const unsigned*)g_hprojb +
                                             (size_t)(b * NS + s) * (NU / 2);
                        float av = 0.f;
#pragma unroll
                        for (int i2 = 0; i2 < 16; i2++) {
                            int u2 = i2 * 32 + lane;
                            unsigned pk = hp[u2];
                            float2 hv = __bfloat1622float2(
                                *reinterpret_cast<const __nv_bfloat162*>(&pk));
                            float4 qw = sQW[u2];
                            av = fmaf(lut_eval(lsig, hv.x + qw.x), qw.z, av);
                            av = fmaf(lut_eval(lsig, hv.y + qw.y), qw.w, av);
                        }
#pragma unroll
                        for (int o = 16; o > 0; o >>= 1)
                            av += __shfl_down_sync(0xffffffffu, av, o);
                        if (lane == 0) g_e[b * NS + s] = lut_eval(lsig, av + be2v);
                    }
                }
                if (tid == 0) s_job = nxt;
                __syncthreads();
                job = s_job;
            }
        }
        gsync(tgt);

        // ==== P4 (static): y reduce + bias + out write; softmax -> alpha ====
        for (int idx = gid; idx < NB * NT; idx += gth) {
            int row = idx >> 9, col = idx & 511;
            float s = 0.f;
#pragma unroll
            for (int ks = 0; ks < 16; ks++) s += g_slaby[(size_t)(ks * NB + row) * NT + col];
            float v = s + by2[col];
            g_y[row * NT + col] = v;
            out[((size_t)row * NS + t) * NT + col] = v;
        }
        if (bid < NB) {
            int b = bid;
            float ev = g_e[b * NS + tid];
            __syncthreads();
            sbuf[tid] = ev;
            __syncthreads();
            for (int o = 128; o > 0; o >>= 1) {
                if (tid < o) sbuf[tid] = fmaxf(sbuf[tid], sbuf[tid + o]);
                __syncthreads();
            }
            float mx = sbuf[0];
            __syncthreads();
            float p = expf(ev - mx);
            sbuf[tid] = p;
            __syncthreads();
            for (int o = 128; o > 0; o >>= 1) {
                if (tid < o) sbuf[tid] += sbuf[tid + o];
                __syncthreads();
            }
            g_a[b * NS + tid] = p * (1.0f / sbuf[0]);
        }
        gsync(tgt);

        // ==== P5 (dynamic): 512 gate-GEMM jobs then 256 context jobs ====
        {
            const int NJ = 512 + 256;
            unsigned* tick = &g_tick[2 * t + 1];
            if (tid == 0) s_job = atomicAdd(tick, 1u);
            __syncthreads();
            int job = s_job;
            while (job < NJ) {
                int nxt = 0;
                if (tid == 0) nxt = atomicAdd(tick, 1u);
                if (job < 512) {
                    int nt = job >> 4, ks = job & 15;
                    int gate = nt >> 3, gc0 = (nt & 7) * 128;
                    const float* W = (gate == 0) ? Wi : (gate == 1) ? Wf
                                   : (gate == 2) ? Wg : Wo;
                    float acc[8][4] = {};
                    XConcatYS xl;
                    gemm_64x128(xl, W, NU, gc0, ks * 96, 6, sbuf, sbuf + 1088, acc);
#pragma unroll
                    for (int i = 0; i < 8; i++)
                        *(float4*)(g_slabg + ((size_t)(ks * NB + wr * 8 + i)) * 4096 +
                                   gate * NU + gc0 + lc) =
                            make_float4(acc[i][0], acc[i][1], acc[i][2], acc[i][3]);
                } else {
                    int cj = job - 512, b = cj >> 2, u0 = (cj & 3) * 256;
                    sbuf[tid] = g_a[b * NS + tid];
                    __syncthreads();
                    int u = u0 + tid;
                    const float* hb = h + (size_t)b * NS * NU + u;
                    float a0 = 0.f, a1 = 0.f, a2 = 0.f, a3 = 0.f;
#pragma unroll 4
                    for (int s2 = 0; s2 < NS; s2 += 4) {
                        a0 = fmaf(hb[(size_t)(s2 + 0) * NU], sbuf[s2 + 0], a0);
                        a1 = fmaf(hb[(size_t)(s2 + 1) * NU], sbuf[s2 + 1], a1);
                        a2 = fmaf(hb[(size_t)(s2 + 2) * NU], sbuf[s2 + 2], a2);
                        a3 = fmaf(hb[(size_t)(s2 + 3) * NU], sbuf[s2 + 3], a3);
                    }
                    g_c[b * NU + u] = (a0 + a1) + (a2 + a3);
                }
                if (tid == 0) s_job = nxt;
                __syncthreads();
                job = s_job;
            }
        }
        gsync(tgt);

        // ==== P6 (static): reduce 16 gate slabs + activations + s' ====
        for (int idx = gid; idx < NB * NU; idx += gth) {
            int b = idx >> 10, u = idx & 1023;
            float iv = bi[u], fv = bf[u], gv = bg[u], ov = bo[u];
#pragma unroll
            for (int ks = 0; ks < 16; ks++) {
                const float* p = g_slabg + (size_t)(ks * NB + b) * 4096 + u;
                iv += p[0];
                fv += p[NU];
                gv += p[2 * NU];
                ov += p[3 * NU];
            }
            iv = lut_eval(lsig, iv);
            fv = lut_eval(lsig, fv);
            gv = lut_eval(ltanh, gv);
            ov = lut_eval(lsig, ov);
            float cn = fmaf(fv, g_c[idx], iv * gv);
            g_s[idx] = ov * lut_eval(ltanh, cn);
        }
        gsync(tgt);
    }
}

// ------------------------- launch --------------------------------------------------
extern "C" void kernel_launch(void* const* d_in, const int* in_sizes, int n_in,
                              void* d_out, int out_size) {
    (void)in_sizes; (void)n_in; (void)out_size;
    const float* h   = (const float*)d_in[0];
    const float* s0  = (const float*)d_in[1];
    const float* Wy1 = (const float*)d_in[2];
    const float* by1 = (const float*)d_in[3];
    const float* Wy2 = (const float*)d_in[4];
    const float* by2 = (const float*)d_in[5];
    const float* We1 = (const float*)d_in[6];
    const float* be1 = (const float*)d_in[7];
    const float* We2 = (const float*)d_in[8];
    const float* be2 = (const float*)d_in[9];
    const float* Wf  = (const float*)d_in[10];
    const float* bf  = (const float*)d_in[11];
    const float* Wi  = (const float*)d_in[12];
    const float* bi  = (const float*)d_in[13];
    const float* Wg  = (const float*)d_in[14];
    const float* bg  = (const float*)d_in[15];
    const float* Wo  = (const float*)d_in[16];
    const float* bo  = (const float*)d_in[17];
    float* out = (float*)d_out;

    int nsm = 148;
    cudaDeviceGetAttribute(&nsm, cudaDevAttrMultiProcessorCount, 0);

    k_init<<<65, NTH>>>(s0);
    k_hproj<<<2048, NTH>>>(h, We1);
    k_persist<<<nsm, NTH>>>(h, Wy1, by1, Wy2, by2, We1, be1, We2, be2,
                            Wi, bi, Wf, bf, Wg, bg, Wo, bo, out);
}

// round 6
// speedup vs baseline: 1.1695x; 1.0248x over previous
#include <cuda_runtime.h>
#include <cuda_bf16.h>
#include <math.h>

#define NB 64
#define NS 256
#define NU 1024
#define NT 512
#define NTH 512

// ------------------------- device scratch -------------------------
__device__ __nv_bfloat16 g_hprojb[NB * NS * NU];  // 32 MB bf16
__device__ float g_s[NB * NU];
__device__ float g_t1[NB * NU];
__device__ float g_q[NB * NU];
__device__ float g_y[NB * NT];
__device__ float g_e[NB * NS];
__device__ float g_a[NB * NS];
__device__ float g_c[NB * NU];
__device__ float g_slab1[16 * NB * 2048];   // t1|q partials, 16 K-slices
__device__ float g_slaby[16 * NB * NT];     // y partials, 16 K-slices
__device__ float g_slabg[24 * NB * 4096];   // gate partials, 24 K-slices (8 y + 16 s)
__device__ float2 g_lut_sig[2049];
__device__ float2 g_lut_tanh[2049];
__device__ unsigned g_cnt;
__device__ unsigned g_phs;
__device__ unsigned g_tick[512];

// ------------------------- LUT activation ------------------------------------------
__device__ __forceinline__ float lut_eval(const float2* __restrict__ lut, float x) {
    float xc = fminf(fmaxf(x, -8.0f), 8.0f);
    float f  = fmaf(xc, 128.0f, 1024.0f);
    float m  = (f - 0.5f) + 12582912.0f;
    int  idx = __float_as_int(m) - 0x4B400000;
    float fr = f - (m - 12582912.0f);
    float2 p = lut[idx];
    return fmaf(fr, p.y, p.x);
}

// ------------------------- grid barrier --------------------------------------------
__device__ __forceinline__ void gsync(unsigned& tgt) {
    tgt++;
    __syncthreads();
    if (threadIdx.x == 0) {
        __threadfence();
        if (atomicAdd(&g_cnt, 1u) == gridDim.x - 1) {
            g_cnt = 0;
            __threadfence();
            atomicExch(&g_phs, tgt);
        } else {
            while (*(volatile unsigned*)&g_phs < tgt) { }
        }
        __threadfence();
    }
    __syncthreads();
}

// ------------------------- init ----------------------------------------------------
__global__ void k_init(const float* __restrict__ s0) {
    int tid = threadIdx.x;
    if (blockIdx.x == 0) {
        if (tid == 0) { g_cnt = 0; g_phs = 0; }
        for (int i = tid; i < 512; i += blockDim.x) g_tick[i] = 0;
        for (int i = tid; i < 2049; i += blockDim.x) {
            float x0 = -8.0f + i * (1.0f / 128.0f);
            float x1 = x0 + (1.0f / 128.0f);
            float sa = 1.0f / (1.0f + expf(-x0));
            float sb = (i == 2048) ? sa : 1.0f / (1.0f + expf(-x1));
            g_lut_sig[i] = make_float2(sa, sb - sa);
            float ta = tanhf(x0);
            float tb = (i == 2048) ? ta : tanhf(x1);
            g_lut_tanh[i] = make_float2(ta, tb - ta);
        }
    } else {
        int b = blockIdx.x - 1;
        for (int u = tid; u < NU; u += blockDim.x) g_s[b * NU + u] = s0[b * NU + u];
    }
}

// ------------------------- GEMM 64x128 tile, 512 threads, double-buffered ----------
struct XGlobal {
    const float* X; int ldx;
    __device__ __forceinline__ float4 ld(int r, int k) const {
        return *(const float4*)(X + (size_t)r * ldx + k);
    }
};
struct XConcatYS {   // x_h = [y (512) | s (1024)]
    __device__ __forceinline__ float4 ld(int r, int k) const {
        return (k < NT) ? *(const float4*)(g_y + (size_t)r * NT + k)
                        : *(const float4*)(g_s + (size_t)r * NU + (k - NT));
    }
};

// Xs: 2 x 16 x 68 floats ; Ws: 2 x 16 x 132 floats ; acc[8][2]
template <typename XL>
__device__ __forceinline__ void gemm512(
    const XL& xl, const float* __restrict__ W, int ldw, int wcol0,
    int k0, int nkb, float* __restrict__ Xs, float* __restrict__ Ws, float acc[8][2])
{
    const int tid = threadIdx.x;
    const int xr  = tid & 63;                   // X loader (tid<256)
    const int xk  = ((tid >> 6) & 3) << 2;
    const int wk  = tid >> 5;                   // W loader: 16 k-rows
    const int wn  = (tid & 31) << 2;            // x 32 float4 = 128 cols
    const int r0  = ((tid >> 5) & 7) << 3;      // compute: 8 rows
    const int c0  = ((tid >> 8) << 6) + ((tid & 31) << 1);  // col half + lane*2
    const bool ldx = tid < 256;

    float4 xv, wv;
    if (ldx) xv = xl.ld(xr, k0 + xk);
    wv = *(const float4*)(W + (size_t)(k0 + wk) * ldw + wcol0 + wn);
    int cur = 0;
    for (int kb = 0; kb < nkb; kb++) {
        float* Xc = Xs + cur * 1088;
        float* Wc = Ws + cur * 2112;
        if (ldx) {
            Xc[(xk + 0) * 68 + xr] = xv.x;
            Xc[(xk + 1) * 68 + xr] = xv.y;
            Xc[(xk + 2) * 68 + xr] = xv.z;
            Xc[(xk + 3) * 68 + xr] = xv.w;
        }
        *(float4*)(Wc + wk * 132 + wn) = wv;
        __syncthreads();
        if (kb + 1 < nkb) {
            int kg = k0 + (kb + 1) * 16;
            if (ldx) xv = xl.ld(xr, kg + xk);
            wv = *(const float4*)(W + (size_t)(kg + wk) * ldw + wcol0 + wn);
        }
#pragma unroll
        for (int kk = 0; kk < 16; kk++) {
            float4 a0 = *(const float4*)(Xc + kk * 68 + r0);
            float4 a1 = *(const float4*)(Xc + kk * 68 + r0 + 4);
            float2 b  = *(const float2*)(Wc + kk * 132 + c0);
            float am[8] = {a0.x, a0.y, a0.z, a0.w, a1.x, a1.y, a1.z, a1.w};
#pragma unroll
            for (int i = 0; i < 8; i++) {
                acc[i][0] = fmaf(am[i], b.x, acc[i][0]);
                acc[i][1] = fmaf(am[i], b.y, acc[i][1]);
            }
        }
        cur ^= 1;
    }
    __syncthreads();   // protect buffers for next job
}

// ------------------------- h_proj -> bf16 (once) -----------------------------------
__global__ __launch_bounds__(NTH) void k_hproj(const float* __restrict__ h,
                                               const float* __restrict__ We1) {
    extern __shared__ float hsm[];
    float acc[8][2] = {};
    int mt = blockIdx.x >> 3, nt = blockIdx.x & 7;
    XGlobal xl{h + (size_t)mt * 64 * NU, NU};
    gemm512(xl, We1, NU, nt * 128, 0, 64, hsm, hsm + 2176, acc);
    int r0 = ((threadIdx.x >> 5) & 7) << 3;
    int c0 = ((threadIdx.x >> 8) << 6) + ((threadIdx.x & 31) << 1);
#pragma unroll
    for (int i = 0; i < 8; i++) {
        size_t off = ((size_t)mt * 64 + r0 + i) * NU + nt * 128 + c0;
        *(__nv_bfloat162*)(g_hprojb + off) = __floats2bfloat162_rn(acc[i][0], acc[i][1]);
    }
}

// ------------------------- persistent scan kernel ----------------------------------
__global__ __launch_bounds__(NTH, 1) void k_persist(
    const float* __restrict__ h,
    const float* __restrict__ Wy1, const float* __restrict__ by1,
    const float* __restrict__ Wy2, const float* __restrict__ by2,
    const float* __restrict__ We1, const float* __restrict__ be1,
    const float* __restrict__ We2, const float* __restrict__ be2,
    const float* __restrict__ Wi,  const float* __restrict__ bi,
    const float* __restrict__ Wf,  const float* __restrict__ bf,
    const float* __restrict__ Wg,  const float* __restrict__ bg,
    const float* __restrict__ Wo,  const float* __restrict__ bo,
    float* __restrict__ out)
{
    extern __shared__ char dyn[];
    float2* lsig  = (float2*)dyn;                       // 2049
    float2* ltanh = lsig + 2049;                        // 2049
    float*  work  = (float*)(dyn + 32784);              // 6400 floats
    float*  Xs    = work;                               // 2176
    float*  Ws    = work + 2176;                        // 4224
    int*    s_job = (int*)(dyn + 32784 + 25600);

    const int tid  = threadIdx.x;
    const int bid  = blockIdx.x;
    const int gth  = gridDim.x * NTH;
    const int gid  = bid * NTH + tid;
    const int r0   = ((tid >> 5) & 7) << 3;
    const int c0   = ((tid >> 8) << 6) + ((tid & 31) << 1);
    const int warp = tid >> 5, lane = tid & 31;

    for (int i = tid; i < 2049; i += NTH) { lsig[i] = g_lut_sig[i]; ltanh[i] = g_lut_tanh[i]; }
    __syncthreads();
    const float be2v = be2[0];
    unsigned tgt = 0;

    for (int t = 0; t < NS; t++) {
        // ==== P1 (static, 256 uniform jobs): t1|q GEMM, 16 tiles x 16 K-slices ====
        for (int j = bid; j < 256; j += gridDim.x) {
            int nt = j >> 4, ks = j & 15, col0 = nt * 128, k0 = ks * 64;
            const float* W; int wc;
            if (col0 < NU) { W = Wy1; wc = col0; }
            else           { W = We1 + (size_t)NU * NU; wc = col0 - NU; }
            float acc[8][2] = {};
            XGlobal xl{g_s, NU};
            gemm512(xl, W, NU, wc, k0, 4, Xs, Ws, acc);
#pragma unroll
            for (int i = 0; i < 8; i++)
                *(float2*)(g_slab1 + ((size_t)(ks * NB + r0 + i)) * 2048 + col0 + c0) =
                    make_float2(acc[i][0], acc[i][1]);
        }
        gsync(tgt);

        // ==== P2: reduce 16 slices -> t1 (tanh), q ====
        for (int idx = gid; idx < NB * 2048; idx += gth) {
            int row = idx >> 11, col = idx & 2047;
            float s = 0.f;
#pragma unroll
            for (int ks = 0; ks < 16; ks++) s += g_slab1[(size_t)(ks * NB + row) * 2048 + col];
            if (col < NU) g_t1[row * NU + col] = lut_eval(ltanh, s + by1[col]);
            else          g_q[row * NU + (col - NU)] = s + be1[col - NU];
        }
        gsync(tgt);

        // ==== P3 (dynamic, 832 jobs): s-part gates (512) + y GEMM (64) + energies (256)
        {
            const int NJ = 832;
            unsigned* tick = &g_tick[2 * t];
            if (tid == 0) *s_job = atomicAdd(tick, 1u);
            __syncthreads();
            int job = *s_job;
            while (job < NJ) {
                int nxt = 0;
                if (tid == 0) nxt = atomicAdd(tick, 1u);
                int jm = (job * 5) % NJ;      // interleave FMA and DRAM jobs
                if (jm < 512) {
                    int tile = jm >> 4, ge = 8 + (jm & 15);
                    int gate = tile >> 3, gc0 = (tile & 7) * 128;
                    const float* W = (gate == 0) ? Wi : (gate == 1) ? Wf
                                   : (gate == 2) ? Wg : Wo;
                    float acc[8][2] = {};
                    XConcatYS xl;
                    gemm512(xl, W, NU, gc0, ge * 64, 4, Xs, Ws, acc);
#pragma unroll
                    for (int i = 0; i < 8; i++)
                        *(float2*)(g_slabg + ((size_t)(ge * NB + r0 + i)) * 4096 +
                                   gate * NU + gc0 + c0) =
                            make_float2(acc[i][0], acc[i][1]);
                } else if (jm < 576) {
                    int yj = jm - 512, nt = yj >> 4, ks = yj & 15, col0 = nt * 128;
                    float acc[8][2] = {};
                    XGlobal xl{g_t1, NU};
                    gemm512(xl, Wy2, NT, col0, ks * 64, 4, Xs, Ws, acc);
#pragma unroll
                    for (int i = 0; i < 8; i++)
                        *(float2*)(g_slaby + ((size_t)(ks * NB + r0 + i)) * NT + col0 + c0) =
                            make_float2(acc[i][0], acc[i][1]);
                } else {
                    int e = jm - 576, b = e >> 2, sg = e & 3;
                    float4* sQW = (float4*)work;
                    const float2* qp = (const float2*)(g_q + (size_t)b * NU);
                    const float2* wp = (const float2*)We2;
                    {
                        float2 qa = qp[tid], wa = wp[tid];
                        sQW[tid] = make_float4(qa.x, qa.y, wa.x, wa.y);
                    }
                    __syncthreads();
#pragma unroll
                    for (int r = 0; r < 4; r++) {
                        int s = sg * 64 + warp * 4 + r;
                        const unsigned* hp = (const unsigned*)g_hprojb +
                                             (size_t)(b * NS + s) * (NU / 2);
                        float av = 0.f;
#pragma unroll
                        for (int i2 = 0; i2 < 16; i2++) {
                            int u2 = i2 * 32 + lane;
                            unsigned pk = hp[u2];
                            float2 hv = __bfloat1622float2(
                                *reinterpret_cast<const __nv_bfloat162*>(&pk));
                            float4 qw = sQW[u2];
                            av = fmaf(lut_eval(lsig, hv.x + qw.x), qw.z, av);
                            av = fmaf(lut_eval(lsig, hv.y + qw.y), qw.w, av);
                        }
#pragma unroll
                        for (int o = 16; o > 0; o >>= 1)
                            av += __shfl_down_sync(0xffffffffu, av, o);
                        if (lane == 0) g_e[b * NS + s] = lut_eval(lsig, av + be2v);
                    }
                }
                if (tid == 0) *s_job = nxt;
                __syncthreads();
                job = *s_job;
            }
        }
        gsync(tgt);

        // ==== P4: y reduce + out write; softmax -> alpha ====
        for (int idx = gid; idx < NB * NT; idx += gth) {
            int row = idx >> 9, col = idx & 511;
            float s = 0.f;
#pragma unroll
            for (int ks = 0; ks < 16; ks++) s += g_slaby[(size_t)(ks * NB + row) * NT + col];
            float v = s + by2[col];
            g_y[row * NT + col] = v;
            out[((size_t)row * NS + t) * NT + col] = v;
        }
        if (bid < NB) {
            int b = bid;
            float ev = (tid < NS) ? g_e[b * NS + tid] : -1e30f;
            __syncthreads();
            work[tid] = ev;
            __syncthreads();
            for (int o = 256; o > 0; o >>= 1) {
                if (tid < o) work[tid] = fmaxf(work[tid], work[tid + o]);
                __syncthreads();
            }
            float mx = work[0];
            __syncthreads();
            float p = expf(ev - mx);
            work[tid] = p;
            __syncthreads();
            for (int o = 256; o > 0; o >>= 1) {
                if (tid < o) work[tid] += work[tid + o];
                __syncthreads();
            }
            if (tid < NS) g_a[b * NS + tid] = p * (1.0f / work[0]);
        }
        gsync(tgt);

        // ==== P5 (dynamic, 384 jobs): y-part gates (256) + context (128) ====
        {
            const int NJ = 384;
            unsigned* tick = &g_tick[2 * t + 1];
            if (tid == 0) *s_job = atomicAdd(tick, 1u);
            __syncthreads();
            int job = *s_job;
            while (job < NJ) {
                int nxt = 0;
                if (tid == 0) nxt = atomicAdd(tick, 1u);
                int jm = (job * 5) % NJ;
                if (jm < 256) {
                    int tile = jm >> 3, ge = jm & 7;
                    int gate = tile >> 3, gc0 = (tile & 7) * 128;
                    const float* W = (gate == 0) ? Wi : (gate == 1) ? Wf
                                   : (gate == 2) ? Wg : Wo;
                    float acc[8][2] = {};
                    XConcatYS xl;
                    gemm512(xl, W, NU, gc0, ge * 64, 4, Xs, Ws, acc);
#pragma unroll
                    for (int i = 0; i < 8; i++)
                        *(float2*)(g_slabg + ((size_t)((8 + ge) * NB + r0 + i)) * 4096 +
                                   gate * NU + gc0 + c0 - 8 * (size_t)NB * 4096) =
                            make_float2(acc[i][0], acc[i][1]);
                } else {
                    int cj = jm - 256, b = cj >> 1, u0 = (cj & 1) * 512;
                    if (tid < NS) work[tid] = g_a[b * NS + tid];
                    __syncthreads();
                    int u = u0 + tid;
                    const float* hb = h + (size_t)b * NS * NU + u;
                    float a0 = 0.f, a1 = 0.f, a2 = 0.f, a3 = 0.f;
#pragma unroll 4
                    for (int s2 = 0; s2 < NS; s2 += 4) {
                        a0 = fmaf(hb[(size_t)(s2 + 0) * NU], work[s2 + 0], a0);
                        a1 = fmaf(hb[(size_t)(s2 + 1) * NU], work[s2 + 1], a1);
                        a2 = fmaf(hb[(size_t)(s2 + 2) * NU], work[s2 + 2], a2);
                        a3 = fmaf(hb[(size_t)(s2 + 3) * NU], work[s2 + 3], a3);
                    }
                    g_c[b * NU + u] = (a0 + a1) + (a2 + a3);
                }
                if (tid == 0) *s_job = nxt;
                __syncthreads();
                job = *s_job;
            }
        }
        gsync(tgt);

        // ==== P6: reduce 24 gate slices + activations + s' ====
        for (int idx = gid; idx < NB * NU; idx += gth) {
            int b = idx >> 10, u = idx & 1023;
            float iv = bi[u], fv = bf[u], gv = bg[u], ov = bo[u];
#pragma unroll
            for (int ge = 0; ge < 24; ge++) {
                const float* p = g_slabg + (size_t)(ge * NB + b) * 4096 + u;
                iv += p[0];
                fv += p[NU];
                gv += p[2 * NU];
                ov += p[3 * NU];
            }
            iv = lut_eval(lsig, iv);
            fv = lut_eval(lsig, fv);
            gv = lut_eval(ltanh, gv);
            ov = lut_eval(lsig, ov);
            float cn = fmaf(fv, g_c[idx], iv * gv);
            g_s[idx] = ov * lut_eval(ltanh, cn);
        }
        gsync(tgt);
    }
}

// ------------------------- launch --------------------------------------------------
extern "C" void kernel_launch(void* const* d_in, const int* in_sizes, int n_in,
                              void* d_out, int out_size) {
    (void)in_sizes; (void)n_in; (void)out_size;
    const float* h   = (const float*)d_in[0];
    const float* s0  = (const float*)d_in[1];
    const float* Wy1 = (const float*)d_in[2];
    const float* by1 = (const float*)d_in[3];
    const float* Wy2 = (const float*)d_in[4];
    const float* by2 = (const float*)d_in[5];
    const float* We1 = (const float*)d_in[6];
    const float* be1 = (const float*)d_in[7];
    const float* We2 = (const float*)d_in[8];
    const float* be2 = (const float*)d_in[9];
    const float* Wf  = (const float*)d_in[10];
    const float* bf  = (const float*)d_in[11];
    const float* Wi  = (const float*)d_in[12];
    const float* bi  = (const float*)d_in[13];
    const float* Wg  = (const float*)d_in[14];
    const float* bg  = (const float*)d_in[15];
    const float* Wo  = (const float*)d_in[16];
    const float* bo  = (const float*)d_in[17];
    float* out = (float*)d_out;

    int nsm = 148;
    cudaDeviceGetAttribute(&nsm, cudaDevAttrMultiProcessorCount, 0);

    static int smem_set = 0;
    const int PSMEM = 32784 + 25600 + 16;
    if (!smem_set) {
        cudaFuncSetAttribute(k_persist, cudaFuncAttributeMaxDynamicSharedMemorySize, PSMEM);
        smem_set = 1;
    }

    k_init<<<65, 256>>>(s0);
    k_hproj<<<2048, NTH, 25600>>>(h, We1);
    k_persist<<<nsm, NTH, PSMEM>>>(h, Wy1, by1, Wy2, by2, We1, be1, We2, be2,
                                   Wi, bi, Wf, bf, Wg, bg, Wo, bo, out);
}

// round 7
// speedup vs baseline: 1.1847x; 1.0129x over previous
#include <cuda_runtime.h>
#include <cuda_bf16.h>
#include <math.h>

#define NB 64
#define NS 256
#define NU 1024
#define NT 512
#define NTH 512

// ------------------------- device scratch -------------------------
__device__ __nv_bfloat16 g_hprojb[NB * NS * NU];  // 32 MB bf16 (phase A)
__device__ __nv_bfloat16 g_hb[NB * NS * NU];      // 32 MB bf16 copy of h (phase A)
__device__ float g_s[NB * NU];
__device__ float g_t1[NB * NU];
__device__ float g_q[NB * NU];
__device__ float g_y[NB * NT];
__device__ float g_e[NB * NS];
__device__ float g_a[NB * NS];
__device__ float g_c[NB * NU];
__device__ float g_slab1[16 * NB * 2048];
__device__ float g_slaby[16 * NB * NT];
__device__ float g_slabg[24 * NB * 4096];
__device__ float2 g_lut_sig[2049];
__device__ float2 g_lut_tanh[2049];
__device__ unsigned g_cnt, g_phs;
__device__ unsigned g_tick[512];

// ------------------------- LUT activation ------------------------------------------
__device__ __forceinline__ float lut_eval(const float2* __restrict__ lut, float x) {
    float xc = fminf(fmaxf(x, -8.0f), 8.0f);
    float f  = fmaf(xc, 128.0f, 1024.0f);
    float m  = (f - 0.5f) + 12582912.0f;
    int  idx = __float_as_int(m) - 0x4B400000;
    float fr = f - (m - 12582912.0f);
    float2 p = lut[idx];
    return fmaf(fr, p.y, p.x);
}

// ------------------------- grid barrier: release-only, no acquire IVALL ------------
// All cross-CTA scan data is read via ld.cg/L2 (coherence point), so no L1
// invalidate is needed on the consumer side. Static data stays L1-cached.
__device__ __forceinline__ void gsync(unsigned& tgt) {
    tgt++;
    __syncthreads();
    if (threadIdx.x == 0) {
        __threadfence();                      // release
        if (atomicAdd(&g_cnt, 1u) == gridDim.x - 1) {
            g_cnt = 0;
            __threadfence();
            atomicExch(&g_phs, tgt);
        } else {
            while (*(volatile unsigned*)&g_phs < tgt) { }
        }
    }
    __syncthreads();
}

// ------------------------- init (1 block): LUTs + barrier/ticket reset -------------
__global__ void k_init() {
    int tid = threadIdx.x;
    if (tid == 0) { g_cnt = 0; g_phs = 0; }
    for (int i = tid; i < 512; i += NTH) g_tick[i] = 0;
    for (int i = tid; i < 2049; i += NTH) {
        float x0 = -8.0f + i * (1.0f / 128.0f);
        float x1 = x0 + (1.0f / 128.0f);
        float sa = 1.0f / (1.0f + expf(-x0));
        float sb = (i == 2048) ? sa : 1.0f / (1.0f + expf(-x1));
        g_lut_sig[i] = make_float2(sa, sb - sa);
        float ta = tanhf(x0);
        float tb = (i == 2048) ? ta : tanhf(x1);
        g_lut_tanh[i] = make_float2(ta, tb - ta);
    }
}

// ------------------------- X loaders -----------------------------------------------
struct XS {    // g_s (scan-mutable -> cg)
    __device__ __forceinline__ float4 ld(int r, int k) const {
        return __ldcg((const float4*)(g_s + (size_t)r * NU + k));
    }
};
struct XT1 {   // g_t1 (scan-mutable -> cg)
    __device__ __forceinline__ float4 ld(int r, int k) const {
        return __ldcg((const float4*)(g_t1 + (size_t)r * NU + k));
    }
};
struct XH {    // input h (static -> streaming)
    const float* base;
    __device__ __forceinline__ float4 ld(int r, int k) const {
        return __ldcs((const float4*)(base + (size_t)r * NU + k));
    }
};
struct XYS {   // [y | s] (scan-mutable -> cg)
    __device__ __forceinline__ float4 ld(int r, int k) const {
        return (k < NT) ? __ldcg((const float4*)(g_y + (size_t)r * NT + k))
                        : __ldcg((const float4*)(g_s + (size_t)r * NU + (k - NT)));
    }
};

// ------------------------- GEMM 64x256 tile, 512 threads, double-buffered ----------
// Per kk per SM: FFMA 256 cyc vs LDS 192 cyc -> FFMA-bound (crossbar headroom).
template <typename XL>
__device__ __forceinline__ void gemm(
    const XL& xl, const float* __restrict__ W, int ldw, int wcol0,
    int k0, int nkb, float* __restrict__ Xs, float* __restrict__ Ws, float acc[8][4])
{
    const int tid = threadIdx.x;
    const int xr  = tid & 63;
    const int xk  = ((tid >> 6) & 3) << 2;
    const bool lx = tid < 256;
    const int wk  = tid >> 6;                 // 8 k-rows x 2 passes
    const int wn  = (tid & 63) << 2;          // 64 float4 = 256 cols
    const int r0  = ((tid >> 5) & 7) << 3;    // 8 row-groups of 8
    const int c0  = ((tid >> 8) << 7) + ((tid & 31) << 2);  // col-half*128 + lane*4

    float4 xv, wv0, wv1;
    if (lx) xv = xl.ld(xr, k0 + xk);
    {
        const float* wp = W + (size_t)(k0 + wk) * ldw + wcol0 + wn;
        wv0 = *(const float4*)wp;
        wv1 = *(const float4*)(wp + 8 * (size_t)ldw);
    }
    int cur = 0;
    for (int kb = 0; kb < nkb; kb++) {
        float* Xc = Xs + cur * 1088;
        float* Wc = Ws + cur * 4224;
        if (lx) {
            Xc[(xk + 0) * 68 + xr] = xv.x;
            Xc[(xk + 1) * 68 + xr] = xv.y;
            Xc[(xk + 2) * 68 + xr] = xv.z;
            Xc[(xk + 3) * 68 + xr] = xv.w;
        }
        *(float4*)(Wc + wk * 264 + wn)       = wv0;
        *(float4*)(Wc + (wk + 8) * 264 + wn) = wv1;
        __syncthreads();
        if (kb + 1 < nkb) {
            int kg = k0 + (kb + 1) * 16;
            if (lx) xv = xl.ld(xr, kg + xk);
            const float* wp = W + (size_t)(kg + wk) * ldw + wcol0 + wn;
            wv0 = *(const float4*)wp;
            wv1 = *(const float4*)(wp + 8 * (size_t)ldw);
        }
#pragma unroll
        for (int kk = 0; kk < 16; kk++) {
            float4 a0 = *(const float4*)(Xc + kk * 68 + r0);
            float4 a1 = *(const float4*)(Xc + kk * 68 + r0 + 4);
            float4 b  = *(const float4*)(Wc + kk * 264 + c0);
            float am[8] = {a0.x, a0.y, a0.z, a0.w, a1.x, a1.y, a1.z, a1.w};
#pragma unroll
            for (int i = 0; i < 8; i++) {
                acc[i][0] = fmaf(am[i], b.x, acc[i][0]);
                acc[i][1] = fmaf(am[i], b.y, acc[i][1]);
                acc[i][2] = fmaf(am[i], b.z, acc[i][2]);
                acc[i][3] = fmaf(am[i], b.w, acc[i][3]);
            }
        }
        cur ^= 1;
    }
    __syncthreads();
}

// ------------------------- the mega-kernel -----------------------------------------
__global__ __launch_bounds__(NTH, 1) void k_all(
    const float* __restrict__ h,  const float* __restrict__ s0,
    const float* __restrict__ Wy1, const float* __restrict__ by1,
    const float* __restrict__ Wy2, const float* __restrict__ by2,
    const float* __restrict__ We1, const float* __restrict__ be1,
    const float* __restrict__ We2, const float* __restrict__ be2,
    const float* __restrict__ Wi,  const float* __restrict__ bi,
    const float* __restrict__ Wf,  const float* __restrict__ bf,
    const float* __restrict__ Wg,  const float* __restrict__ bg,
    const float* __restrict__ Wo,  const float* __restrict__ bo,
    float* __restrict__ out)
{
    extern __shared__ char dyn[];
    float2* lsig  = (float2*)dyn;
    float2* ltanh = (float2*)(dyn + 16392);
    float*  Xs    = (float*)(dyn + 32784);   // 2x1088 floats (also "work" buffer)
    float*  Ws    = (float*)(dyn + 41488);   // 2x4224 floats
    int*    s_job = (int*)(dyn + 75280);
    float*  work  = Xs;

    const int tid  = threadIdx.x;
    const int bid  = blockIdx.x;
    const int gth  = gridDim.x * NTH;
    const int gid  = bid * NTH + tid;
    const int r0   = ((tid >> 5) & 7) << 3;
    const int c0   = ((tid >> 8) << 7) + ((tid & 31) << 2);
    const int warp = tid >> 5, lane = tid & 31;

    for (int i = tid; i < 2049; i += NTH) { lsig[i] = g_lut_sig[i]; ltanh[i] = g_lut_tanh[i]; }
    __syncthreads();
    const float be2v = be2[0];
    unsigned tgt = 0;

    // ==== Phase A: h_proj -> bf16 (1024 jobs), h -> bf16 copy, s0 -> g_s ====
    {
        const float* We1h = We1;   // first NU rows
        for (int j = bid; j < 1024; j += gridDim.x) {
            int mt = j >> 2, nt = j & 3;
            float acc[8][4] = {};
            XH xl{h + (size_t)mt * 64 * NU};
            gemm(xl, We1h, NU, nt * 256, 0, 64, Xs, Ws, acc);
#pragma unroll
            for (int i = 0; i < 8; i++) {
                size_t off = ((size_t)mt * 64 + r0 + i) * NU + nt * 256 + c0;
                __nv_bfloat162 lo = __floats2bfloat162_rn(acc[i][0], acc[i][1]);
                __nv_bfloat162 hi = __floats2bfloat162_rn(acc[i][2], acc[i][3]);
                *(uint2*)(g_hprojb + off) =
                    make_uint2(*(unsigned*)&lo, *(unsigned*)&hi);
            }
        }
        for (size_t idx = gid; idx < (size_t)NB * NS * NU / 4; idx += gth) {
            float4 v = __ldcs((const float4*)h + idx);
            __nv_bfloat162 lo = __floats2bfloat162_rn(v.x, v.y);
            __nv_bfloat162 hi = __floats2bfloat162_rn(v.z, v.w);
            *(uint2*)(g_hb + idx * 4) = make_uint2(*(unsigned*)&lo, *(unsigned*)&hi);
        }
        for (int idx = gid; idx < NB * NU; idx += gth) g_s[idx] = s0[idx];
    }
    gsync(tgt);

    for (int t = 0; t < NS; t++) {
        // ==== P1 (static, 128 jobs): t1|q GEMM, 8 tiles(256) x 16 K-slices ====
        for (int j = bid; j < 128; j += gridDim.x) {
            int nt = j >> 4, ks = j & 15, col0 = nt * 256, k0 = ks * 64;
            const float* W; int wc;
            if (nt < 4) { W = Wy1; wc = col0; }
            else        { W = We1 + (size_t)NU * NU; wc = col0 - NU; }
            float acc[8][4] = {};
            XS xl;
            gemm(xl, W, NU, wc, k0, 4, Xs, Ws, acc);
#pragma unroll
            for (int i = 0; i < 8; i++)
                *(float4*)(g_slab1 + ((size_t)(ks * NB + r0 + i)) * 2048 + col0 + c0) =
                    make_float4(acc[i][0], acc[i][1], acc[i][2], acc[i][3]);
        }
        gsync(tgt);

        // ==== P2: reduce 16 slices -> t1 (tanh), q (float4) ====
        for (int idx = gid; idx < NB * 512; idx += gth) {
            int row = idx >> 9, col = (idx & 511) << 2;
            float4 s = make_float4(0.f, 0.f, 0.f, 0.f);
#pragma unroll
            for (int ks = 0; ks < 16; ks++) {
                float4 v = __ldcg((const float4*)(g_slab1 +
                              (size_t)(ks * NB + row) * 2048 + col));
                s.x += v.x; s.y += v.y; s.z += v.z; s.w += v.w;
            }
            if (col < NU) {
                float4 bb = *(const float4*)(by1 + col);
                *(float4*)(g_t1 + (size_t)row * NU + col) = make_float4(
                    lut_eval(ltanh, s.x + bb.x), lut_eval(ltanh, s.y + bb.y),
                    lut_eval(ltanh, s.z + bb.z), lut_eval(ltanh, s.w + bb.w));
            } else {
                int cq = col - NU;
                float4 bb = *(const float4*)(be1 + cq);
                *(float4*)(g_q + (size_t)row * NU + cq) = make_float4(
                    s.x + bb.x, s.y + bb.y, s.z + bb.z, s.w + bb.w);
            }
        }
        gsync(tgt);

        // ==== P3 (dynamic, 544 jobs): gate-s GEMM (256) + y GEMM (32) + energies (256)
        {
            const int NJ = 544;
            unsigned* tick = &g_tick[2 * t];
            if (tid == 0) *s_job = atomicAdd(tick, 1u);
            __syncthreads();
            int job = *s_job;
            while (job < NJ) {
                int nxt = 0;
                if (tid == 0) nxt = atomicAdd(tick, 1u);
                int jm = (job * 5) % NJ;
                if (jm < 256) {
                    int tile = jm >> 4, ge = 8 + (jm & 15);
                    int gate = tile >> 2, tn = tile & 3;
                    const float* W = (gate == 0) ? Wi : (gate == 1) ? Wf
                                   : (gate == 2) ? Wg : Wo;
                    float acc[8][4] = {};
                    XYS xl;
                    gemm(xl, W, NU, tn * 256, ge * 64, 4, Xs, Ws, acc);
#pragma unroll
                    for (int i = 0; i < 8; i++)
                        *(float4*)(g_slabg + ((size_t)(ge * NB + r0 + i)) * 4096 +
                                   gate * NU + tn * 256 + c0) =
                            make_float4(acc[i][0], acc[i][1], acc[i][2], acc[i][3]);
                } else if (jm < 288) {
                    int yj = jm - 256, tn = yj >> 4, ks = yj & 15;
                    float acc[8][4] = {};
                    XT1 xl;
                    gemm(xl, Wy2, NT, tn * 256, ks * 64, 4, Xs, Ws, acc);
#pragma unroll
                    for (int i = 0; i < 8; i++)
                        *(float4*)(g_slaby + ((size_t)(ks * NB + r0 + i)) * NT +
                                   tn * 256 + c0) =
                            make_float4(acc[i][0], acc[i][1], acc[i][2], acc[i][3]);
                } else {
                    int e = jm - 288, b = e >> 2, sg = e & 3;
                    float4* sQW = (float4*)work;
                    float2 qa = __ldcg((const float2*)(g_q + (size_t)b * NU) + tid);
                    float2 wa = *((const float2*)We2 + tid);
                    sQW[tid] = make_float4(qa.x, qa.y, wa.x, wa.y);
                    __syncthreads();
#pragma unroll
                    for (int r = 0; r < 4; r++) {
                        int s = sg * 64 + warp * 4 + r;
                        const unsigned* hp = (const unsigned*)g_hprojb +
                                             (size_t)(b * NS + s) * (NU / 2);
                        float av = 0.f;
#pragma unroll
                        for (int i2 = 0; i2 < 16; i2++) {
                            int u2 = i2 * 32 + lane;
                            unsigned pk = __ldcg(hp + u2);
                            float2 hv = __bfloat1622float2(
                                *reinterpret_cast<const __nv_bfloat162*>(&pk));
                            float4 qw = sQW[u2];
                            av = fmaf(lut_eval(lsig, hv.x + qw.x), qw.z, av);
                            av = fmaf(lut_eval(lsig, hv.y + qw.y), qw.w, av);
                        }
#pragma unroll
                        for (int o = 16; o > 0; o >>= 1)
                            av += __shfl_down_sync(0xffffffffu, av, o);
                        if (lane == 0) g_e[b * NS + s] = lut_eval(lsig, av + be2v);
                    }
                }
                if (tid == 0) *s_job = nxt;
                __syncthreads();
                job = *s_job;
            }
        }
        gsync(tgt);

        // ==== P4: y reduce + out write (float4); softmax -> alpha ====
        for (int idx = gid; idx < NB * 128; idx += gth) {
            int row = idx >> 7, col = (idx & 127) << 2;
            float4 s = make_float4(0.f, 0.f, 0.f, 0.f);
#pragma unroll
            for (int ks = 0; ks < 16; ks++) {
                float4 v = __ldcg((const float4*)(g_slaby +
                              (size_t)(ks * NB + row) * NT + col));
                s.x += v.x; s.y += v.y; s.z += v.z; s.w += v.w;
            }
            float4 bb = *(const float4*)(by2 + col);
            float4 vv = make_float4(s.x + bb.x, s.y + bb.y, s.z + bb.z, s.w + bb.w);
            *(float4*)(g_y + (size_t)row * NT + col) = vv;
            *(float4*)(out + ((size_t)row * NS + t) * NT + col) = vv;
        }
        if (bid < NB) {
            int b = bid;
            float ev = (tid < NS) ? __ldcg(g_e + b * NS + tid) : -1e30f;
            __syncthreads();
            work[tid] = ev;
            __syncthreads();
            for (int o = 256; o > 0; o >>= 1) {
                if (tid < o) work[tid] = fmaxf(work[tid], work[tid + o]);
                __syncthreads();
            }
            float mx = work[0];
            __syncthreads();
            float p = expf(ev - mx);
            work[tid] = p;
            __syncthreads();
            for (int o = 256; o > 0; o >>= 1) {
                if (tid < o) work[tid] += work[tid + o];
                __syncthreads();
            }
            if (tid < NS) g_a[b * NS + tid] = p * (1.0f / work[0]);
        }
        gsync(tgt);

        // ==== P5 (dynamic, 192 jobs): gate-y GEMM (128) + context (64) ====
        {
            const int NJ = 192;
            unsigned* tick = &g_tick[2 * t + 1];
            if (tid == 0) *s_job = atomicAdd(tick, 1u);
            __syncthreads();
            int job = *s_job;
            while (job < NJ) {
                int nxt = 0;
                if (tid == 0) nxt = atomicAdd(tick, 1u);
                int jm = (job * 5) % NJ;
                if (jm < 128) {
                    int tile = jm >> 3, ge = jm & 7;
                    int gate = tile >> 2, tn = tile & 3;
                    const float* W = (gate == 0) ? Wi : (gate == 1) ? Wf
                                   : (gate == 2) ? Wg : Wo;
                    float acc[8][4] = {};
                    XYS xl;
                    gemm(xl, W, NU, tn * 256, ge * 64, 4, Xs, Ws, acc);
#pragma unroll
                    for (int i = 0; i < 8; i++)
                        *(float4*)(g_slabg + ((size_t)(ge * NB + r0 + i)) * 4096 +
                                   gate * NU + tn * 256 + c0) =
                            make_float4(acc[i][0], acc[i][1], acc[i][2], acc[i][3]);
                } else {
                    int b = jm - 128;
                    if (tid < NS) work[tid] = __ldcg(g_a + b * NS + tid);
                    __syncthreads();
                    const unsigned* hb = (const unsigned*)g_hb +
                                         (size_t)b * NS * (NU / 2) + tid;
                    float av0 = 0.f, av1 = 0.f;
#pragma unroll 8
                    for (int s2 = 0; s2 < NS; s2++) {
                        unsigned raw = __ldcg(hb + (size_t)s2 * (NU / 2));
                        float2 f2 = __bfloat1622float2(
                            *reinterpret_cast<const __nv_bfloat162*>(&raw));
                        float aw = work[s2];
                        av0 = fmaf(f2.x, aw, av0);
                        av1 = fmaf(f2.y, aw, av1);
                    }
                    *(float2*)(g_c + (size_t)b * NU + tid * 2) = make_float2(av0, av1);
                }
                if (tid == 0) *s_job = nxt;
                __syncthreads();
                job = *s_job;
            }
        }
        gsync(tgt);

        // ==== P6: reduce 24 gate slices + activations + s' (float4) ====
        for (int idx = gid; idx < NB * 256; idx += gth) {
            int b = idx >> 8, u = (idx & 255) << 2;
            const float* sb = g_slabg + (size_t)b * 4096 + u;
            float4 iv = *(const float4*)(bi + u);
            float4 fv = *(const float4*)(bf + u);
            float4 gv = *(const float4*)(bg + u);
            float4 ov = *(const float4*)(bo + u);
#pragma unroll
            for (int ge = 0; ge < 24; ge++) {
                const float* p = sb + (size_t)ge * NB * 4096;
                float4 a = __ldcg((const float4*)(p));
                float4 bq = __ldcg((const float4*)(p + NU));
                float4 cq = __ldcg((const float4*)(p + 2 * NU));
                float4 dq = __ldcg((const float4*)(p + 3 * NU));
                iv.x += a.x;  iv.y += a.y;  iv.z += a.z;  iv.w += a.w;
                fv.x += bq.x; fv.y += bq.y; fv.z += bq.z; fv.w += bq.w;
                gv.x += cq.x; gv.y += cq.y; gv.z += cq.z; gv.w += cq.w;
                ov.x += dq.x; ov.y += dq.y; ov.z += dq.z; ov.w += dq.w;
            }
            float4 cv = __ldcg((const float4*)(g_c + (size_t)b * NU + u));
            float4 sv;
            {
                float i0 = lut_eval(lsig, iv.x), f0 = lut_eval(lsig, fv.x);
                float gg = lut_eval(ltanh, gv.x), o0 = lut_eval(lsig, ov.x);
                sv.x = o0 * lut_eval(ltanh, fmaf(f0, cv.x, i0 * gg));
                i0 = lut_eval(lsig, iv.y); f0 = lut_eval(lsig, fv.y);
                gg = lut_eval(ltanh, gv.y); o0 = lut_eval(lsig, ov.y);
                sv.y = o0 * lut_eval(ltanh, fmaf(f0, cv.y, i0 * gg));
                i0 = lut_eval(lsig, iv.z); f0 = lut_eval(lsig, fv.z);
                gg = lut_eval(ltanh, gv.z); o0 = lut_eval(lsig, ov.z);
                sv.z = o0 * lut_eval(ltanh, fmaf(f0, cv.z, i0 * gg));
                i0 = lut_eval(lsig, iv.w); f0 = lut_eval(lsig, fv.w);
                gg = lut_eval(ltanh, gv.w); o0 = lut_eval(lsig, ov.w);
                sv.w = o0 * lut_eval(ltanh, fmaf(f0, cv.w, i0 * gg));
            }
            *(float4*)(g_s + (size_t)b * NU + u) = sv;
        }
        gsync(tgt);
    }
}

// ------------------------- launch --------------------------------------------------
extern "C" void kernel_launch(void* const* d_in, const int* in_sizes, int n_in,
                              void* d_out, int out_size) {
    (void)in_sizes; (void)n_in; (void)out_size;
    const float* h   = (const float*)d_in[0];
    const float* s0  = (const float*)d_in[1];
    const float* Wy1 = (const float*)d_in[2];
    const float* by1 = (const float*)d_in[3];
    const float* Wy2 = (const float*)d_in[4];
    const float* by2 = (const float*)d_in[5];
    const float* We1 = (const float*)d_in[6];
    const float* be1 = (const float*)d_in[7];
    const float* We2 = (const float*)d_in[8];
    const float* be2 = (const float*)d_in[9];
    const float* Wf  = (const float*)d_in[10];
    const float* bf  = (const float*)d_in[11];
    const float* Wi  = (const float*)d_in[12];
    const float* bi  = (const float*)d_in[13];
    const float* Wg  = (const float*)d_in[14];
    const float* bg  = (const float*)d_in[15];
    const float* Wo  = (const float*)d_in[16];
    const float* bo  = (const float*)d_in[17];
    float* out = (float*)d_out;

    int nsm = 148;
    cudaDeviceGetAttribute(&nsm, cudaDevAttrMultiProcessorCount, 0);

    const int PSMEM = 75296;
    static int smem_set = 0;
    if (!smem_set) {
        cudaFuncSetAttribute(k_all, cudaFuncAttributeMaxDynamicSharedMemorySize, PSMEM);
        smem_set = 1;
    }

    k_init<<<1, NTH>>>();
    k_all<<<nsm, NTH, PSMEM>>>(h, s0, Wy1, by1, Wy2, by2, We1, be1, We2, be2,
                               Wi, bi, Wf, bf, Wg, bg, Wo, bo, out);
}

// round 8
// speedup vs baseline: 1.1971x; 1.0105x over previous
#include <cuda_runtime.h>
#include <cuda_bf16.h>
#include <math.h>

#define NB 64
#define NS 256
#define NU 1024
#define NT 512
#define NTH 512

// ------------------------- device scratch -------------------------
__device__ __nv_bfloat16 g_hprojb[NB * NS * NU];  // 32 MB bf16 (phase A)
__device__ __nv_bfloat16 g_hb[NB * NS * NU];      // 32 MB bf16 copy of h (phase A)
__device__ float g_s[NB * NU];
__device__ float g_t1[NB * NU];
__device__ float g_q[NB * NU];
__device__ float g_y[NB * NT];
__device__ float g_e[NB * NS];
__device__ float g_a[NB * NS];
__device__ float g_c[NB * NU];
__device__ float g_slab1[16 * NB * 2048];
__device__ float g_slaby[16 * NB * NT];
__device__ float g_slabg[24 * NB * 4096];
__device__ float2 g_lut_sig[2049];
__device__ float2 g_lut_tanh[2049];
__device__ unsigned g_cnt, g_phs;
__device__ unsigned g_tick[512];

// ------------------------- LUT activation ------------------------------------------
__device__ __forceinline__ float lut_eval(const float2* __restrict__ lut, float x) {
    float xc = fminf(fmaxf(x, -8.0f), 8.0f);
    float f  = fmaf(xc, 128.0f, 1024.0f);
    float m  = (f - 0.5f) + 12582912.0f;
    int  idx = __float_as_int(m) - 0x4B400000;
    float fr = f - (m - 12582912.0f);
    float2 p = lut[idx];
    return fmaf(fr, p.y, p.x);
}

// ------------------------- grid barrier: release-only, no acquire IVALL ------------
// All cross-CTA scan data is read via ld.cg/L2 (coherence point), so no L1
// invalidate is needed on the consumer side. Static data stays L1-cached.
__device__ __forceinline__ void gsync(unsigned& tgt) {
    tgt++;
    __syncthreads();
    if (threadIdx.x == 0) {
        __threadfence();                      // release
        if (atomicAdd(&g_cnt, 1u) == gridDim.x - 1) {
            g_cnt = 0;
            __threadfence();
            atomicExch(&g_phs, tgt);
        } else {
            while (*(volatile unsigned*)&g_phs < tgt) { }
        }
    }
    __syncthreads();
}

// ------------------------- init (1 block): LUTs + barrier/ticket reset -------------
__global__ void k_init() {
    int tid = threadIdx.x;
    if (tid == 0) { g_cnt = 0; g_phs = 0; }
    for (int i = tid; i < 512; i += NTH) g_tick[i] = 0;
    for (int i = tid; i < 2049; i += NTH) {
        float x0 = -8.0f + i * (1.0f / 128.0f);
        float x1 = x0 + (1.0f / 128.0f);
        float sa = 1.0f / (1.0f + expf(-x0));
        float sb = (i == 2048) ? sa : 1.0f / (1.0f + expf(-x1));
        g_lut_sig[i] = make_float2(sa, sb - sa);
        float ta = tanhf(x0);
        float tb = (i == 2048) ? ta : tanhf(x1);
        g_lut_tanh[i] = make_float2(ta, tb - ta);
    }
}

// ------------------------- X loaders -----------------------------------------------
struct XS {    // g_s (scan-mutable -> cg)
    __device__ __forceinline__ float4 ld(int r, int k) const {
        return __ldcg((const float4*)(g_s + (size_t)r * NU + k));
    }
};
struct XT1 {   // g_t1 (scan-mutable -> cg)
    __device__ __forceinline__ float4 ld(int r, int k) const {
        return __ldcg((const float4*)(g_t1 + (size_t)r * NU + k));
    }
};
struct XH {    // input h (static -> streaming)
    const float* base;
    __device__ __forceinline__ float4 ld(int r, int k) const {
        return __ldcs((const float4*)(base + (size_t)r * NU + k));
    }
};
struct XYS {   // [y | s] (scan-mutable -> cg)
    __device__ __forceinline__ float4 ld(int r, int k) const {
        return (k < NT) ? __ldcg((const float4*)(g_y + (size_t)r * NT + k))
                        : __ldcg((const float4*)(g_s + (size_t)r * NU + (k - NT)));
    }
};

// ------------------------- GEMM 64x256 tile, 512 threads, double-buffered ----------
// Per kk per SM: FFMA 256 cyc vs LDS 192 cyc -> FFMA-bound (crossbar headroom).
template <typename XL>
__device__ __forceinline__ void gemm(
    const XL& xl, const float* __restrict__ W, int ldw, int wcol0,
    int k0, int nkb, float* __restrict__ Xs, float* __restrict__ Ws, float acc[8][4])
{
    const int tid = threadIdx.x;
    const int xr  = tid & 63;
    const int xk  = ((tid >> 6) & 3) << 2;
    const bool lx = tid < 256;
    const int wk  = tid >> 6;                 // 8 k-rows x 2 passes
    const int wn  = (tid & 63) << 2;          // 64 float4 = 256 cols
    const int r0  = ((tid >> 5) & 7) << 3;    // 8 row-groups of 8
    const int c0  = ((tid >> 8) << 7) + ((tid & 31) << 2);  // col-half*128 + lane*4

    float4 xv, wv0, wv1;
    if (lx) xv = xl.ld(xr, k0 + xk);
    {
        const float* wp = W + (size_t)(k0 + wk) * ldw + wcol0 + wn;
        wv0 = *(const float4*)wp;
        wv1 = *(const float4*)(wp + 8 * (size_t)ldw);
    }
    int cur = 0;
    for (int kb = 0; kb < nkb; kb++) {
        float* Xc = Xs + cur * 1088;
        float* Wc = Ws + cur * 4224;
        if (lx) {
            Xc[(xk + 0) * 68 + xr] = xv.x;
            Xc[(xk + 1) * 68 + xr] = xv.y;
            Xc[(xk + 2) * 68 + xr] = xv.z;
            Xc[(xk + 3) * 68 + xr] = xv.w;
        }
        *(float4*)(Wc + wk * 264 + wn)       = wv0;
        *(float4*)(Wc + (wk + 8) * 264 + wn) = wv1;
        __syncthreads();
        if (kb + 1 < nkb) {
            int kg = k0 + (kb + 1) * 16;
            if (lx) xv = xl.ld(xr, kg + xk);
            const float* wp = W + (size_t)(kg + wk) * ldw + wcol0 + wn;
            wv0 = *(const float4*)wp;
            wv1 = *(const float4*)(wp + 8 * (size_t)ldw);
        }
#pragma unroll
        for (int kk = 0; kk < 16; kk++) {
            float4 a0 = *(const float4*)(Xc + kk * 68 + r0);
            float4 a1 = *(const float4*)(Xc + kk * 68 + r0 + 4);
            float4 b  = *(const float4*)(Wc + kk * 264 + c0);
            float am[8] = {a0.x, a0.y, a0.z, a0.w, a1.x, a1.y, a1.z, a1.w};
#pragma unroll
            for (int i = 0; i < 8; i++) {
                acc[i][0] = fmaf(am[i], b.x, acc[i][0]);
                acc[i][1] = fmaf(am[i], b.y, acc[i][1]);
                acc[i][2] = fmaf(am[i], b.z, acc[i][2]);
                acc[i][3] = fmaf(am[i], b.w, acc[i][3]);
            }
        }
        cur ^= 1;
    }
    __syncthreads();
}

// ------------------------- the mega-kernel -----------------------------------------
__global__ __launch_bounds__(NTH, 1) void k_all(
    const float* __restrict__ h,  const float* __restrict__ s0,
    const float* __restrict__ Wy1, const float* __restrict__ by1,
    const float* __restrict__ Wy2, const float* __restrict__ by2,
    const float* __restrict__ We1, const float* __restrict__ be1,
    const float* __restrict__ We2, const float* __restrict__ be2,
    const float* __restrict__ Wi,  const float* __restrict__ bi,
    const float* __restrict__ Wf,  const float* __restrict__ bf,
    const float* __restrict__ Wg,  const float* __restrict__ bg,
    const float* __restrict__ Wo,  const float* __restrict__ bo,
    float* __restrict__ out)
{
    extern __shared__ char dyn[];
    float2* lsig  = (float2*)dyn;
    float2* ltanh = (float2*)(dyn + 16392);
    float*  Xs    = (float*)(dyn + 32784);   // 2x1088 floats (also "work" buffer)
    float*  Ws    = (float*)(dyn + 41488);   // 2x4224 floats
    int*    s_job = (int*)(dyn + 75280);
    float*  work  = Xs;

    const int tid  = threadIdx.x;
    const int bid  = blockIdx.x;
    const int gth  = gridDim.x * NTH;
    const int gid  = bid * NTH + tid;
    const int r0   = ((tid >> 5) & 7) << 3;
    const int c0   = ((tid >> 8) << 7) + ((tid & 31) << 2);
    const int warp = tid >> 5, lane = tid & 31;

    for (int i = tid; i < 2049; i += NTH) { lsig[i] = g_lut_sig[i]; ltanh[i] = g_lut_tanh[i]; }
    __syncthreads();
    const float be2v = be2[0];
    unsigned tgt = 0;

    // ==== Phase A: h_proj -> bf16 (1024 jobs), h -> bf16 copy, s0 -> g_s ====
    {
        const float* We1h = We1;   // first NU rows
        for (int j = bid; j < 1024; j += gridDim.x) {
            int mt = j >> 2, nt = j & 3;
            float acc[8][4] = {};
            XH xl{h + (size_t)mt * 64 * NU};
            gemm(xl, We1h, NU, nt * 256, 0, 64, Xs, Ws, acc);
#pragma unroll
            for (int i = 0; i < 8; i++) {
                size_t off = ((size_t)mt * 64 + r0 + i) * NU + nt * 256 + c0;
                __nv_bfloat162 lo = __floats2bfloat162_rn(acc[i][0], acc[i][1]);
                __nv_bfloat162 hi = __floats2bfloat162_rn(acc[i][2], acc[i][3]);
                *(uint2*)(g_hprojb + off) =
                    make_uint2(*(unsigned*)&lo, *(unsigned*)&hi);
            }
        }
        for (size_t idx = gid; idx < (size_t)NB * NS * NU / 4; idx += gth) {
            float4 v = __ldcs((const float4*)h + idx);
            __nv_bfloat162 lo = __floats2bfloat162_rn(v.x, v.y);
            __nv_bfloat162 hi = __floats2bfloat162_rn(v.z, v.w);
            *(uint2*)(g_hb + idx * 4) = make_uint2(*(unsigned*)&lo, *(unsigned*)&hi);
        }
        for (int idx = gid; idx < NB * NU; idx += gth) g_s[idx] = s0[idx];
    }
    gsync(tgt);

    for (int t = 0; t < NS; t++) {
        // ==== P1 (static, 128 jobs): t1|q GEMM, 8 tiles(256) x 16 K-slices ====
        for (int j = bid; j < 128; j += gridDim.x) {
            int nt = j >> 4, ks = j & 15, col0 = nt * 256, k0 = ks * 64;
            const float* W; int wc;
            if (nt < 4) { W = Wy1; wc = col0; }
            else        { W = We1 + (size_t)NU * NU; wc = col0 - NU; }
            float acc[8][4] = {};
            XS xl;
            gemm(xl, W, NU, wc, k0, 4, Xs, Ws, acc);
#pragma unroll
            for (int i = 0; i < 8; i++)
                *(float4*)(g_slab1 + ((size_t)(ks * NB + r0 + i)) * 2048 + col0 + c0) =
                    make_float4(acc[i][0], acc[i][1], acc[i][2], acc[i][3]);
        }
        gsync(tgt);

        // ==== P2: reduce 16 slices -> t1 (tanh), q (float4) ====
        for (int idx = gid; idx < NB * 512; idx += gth) {
            int row = idx >> 9, col = (idx & 511) << 2;
            float4 s = make_float4(0.f, 0.f, 0.f, 0.f);
#pragma unroll
            for (int ks = 0; ks < 16; ks++) {
                float4 v = __ldcg((const float4*)(g_slab1 +
                              (size_t)(ks * NB + row) * 2048 + col));
                s.x += v.x; s.y += v.y; s.z += v.z; s.w += v.w;
            }
            if (col < NU) {
                float4 bb = *(const float4*)(by1 + col);
                *(float4*)(g_t1 + (size_t)row * NU + col) = make_float4(
                    lut_eval(ltanh, s.x + bb.x), lut_eval(ltanh, s.y + bb.y),
                    lut_eval(ltanh, s.z + bb.z), lut_eval(ltanh, s.w + bb.w));
            } else {
                int cq = col - NU;
                float4 bb = *(const float4*)(be1 + cq);
                *(float4*)(g_q + (size_t)row * NU + cq) = make_float4(
                    s.x + bb.x, s.y + bb.y, s.z + bb.z, s.w + bb.w);
            }
        }
        gsync(tgt);

        // ==== P3 (dynamic, 544 jobs): gate-s GEMM (256) + y GEMM (32) + energies (256)
        {
            const int NJ = 544;
            unsigned* tick = &g_tick[2 * t];
            if (tid == 0) *s_job = atomicAdd(tick, 1u);
            __syncthreads();
            int job = *s_job;
            while (job < NJ) {
                int nxt = 0;
                if (tid == 0) nxt = atomicAdd(tick, 1u);
                int jm = (job * 5) % NJ;
                if (jm < 256) {
                    int tile = jm >> 4, ge = 8 + (jm & 15);
                    int gate = tile >> 2, tn = tile & 3;
                    const float* W = (gate == 0) ? Wi : (gate == 1) ? Wf
                                   : (gate == 2) ? Wg : Wo;
                    float acc[8][4] = {};
                    XYS xl;
                    gemm(xl, W, NU, tn * 256, ge * 64, 4, Xs, Ws, acc);
#pragma unroll
                    for (int i = 0; i < 8; i++)
                        *(float4*)(g_slabg + ((size_t)(ge * NB + r0 + i)) * 4096 +
                                   gate * NU + tn * 256 + c0) =
                            make_float4(acc[i][0], acc[i][1], acc[i][2], acc[i][3]);
                } else if (jm < 288) {
                    int yj = jm - 256, tn = yj >> 4, ks = yj & 15;
                    float acc[8][4] = {};
                    XT1 xl;
                    gemm(xl, Wy2, NT, tn * 256, ks * 64, 4, Xs, Ws, acc);
#pragma unroll
                    for (int i = 0; i < 8; i++)
                        *(float4*)(g_slaby + ((size_t)(ks * NB + r0 + i)) * NT +
                                   tn * 256 + c0) =
                            make_float4(acc[i][0], acc[i][1], acc[i][2], acc[i][3]);
                } else {
                    int e = jm - 288, b = e >> 2, sg = e & 3;
                    float4* sQW = (float4*)work;
                    float2 qa = __ldcg((const float2*)(g_q + (size_t)b * NU) + tid);
                    float2 wa = *((const float2*)We2 + tid);
                    sQW[tid] = make_float4(qa.x, qa.y, wa.x, wa.y);
                    __syncthreads();
#pragma unroll
                    for (int r = 0; r < 4; r++) {
                        int s = sg * 64 + warp * 4 + r;
                        const unsigned* hp = (const unsigned*)g_hprojb +
                                             (size_t)(b * NS + s) * (NU / 2);
                        float av = 0.f;
#pragma unroll
                        for (int i2 = 0; i2 < 16; i2++) {
                            int u2 = i2 * 32 + lane;
                            unsigned pk = __ldcg(hp + u2);
                            float2 hv = __bfloat1622float2(
                                *reinterpret_cast<const __nv_bfloat162*>(&pk));
                            float4 qw = sQW[u2];
                            av = fmaf(lut_eval(lsig, hv.x + qw.x), qw.z, av);
                            av = fmaf(lut_eval(lsig, hv.y + qw.y), qw.w, av);
                        }
#pragma unroll
                        for (int o = 16; o > 0; o >>= 1)
                            av += __shfl_down_sync(0xffffffffu, av, o);
                        if (lane == 0) g_e[b * NS + s] = lut_eval(lsig, av + be2v);
                    }
                }
                if (tid == 0) *s_job = nxt;
                __syncthreads();
                job = *s_job;
            }
        }
        gsync(tgt);

        // ==== P4: y reduce + out write (float4); softmax -> alpha ====
        for (int idx = gid; idx < NB * 128; idx += gth) {
            int row = idx >> 7, col = (idx & 127) << 2;
            float4 s = make_float4(0.f, 0.f, 0.f, 0.f);
#pragma unroll
            for (int ks = 0; ks < 16; ks++) {
                float4 v = __ldcg((const float4*)(g_slaby +
                              (size_t)(ks * NB + row) * NT + col));
                s.x += v.x; s.y += v.y; s.z += v.z; s.w += v.w;
            }
            float4 bb = *(const float4*)(by2 + col);
            float4 vv = make_float4(s.x + bb.x, s.y + bb.y, s.z + bb.z, s.w + bb.w);
            *(float4*)(g_y + (size_t)row * NT + col) = vv;
            *(float4*)(out + ((size_t)row * NS + t) * NT + col) = vv;
        }
        if (bid < NB) {
            int b = bid;
            float ev = (tid < NS) ? __ldcg(g_e + b * NS + tid) : -1e30f;
            __syncthreads();
            work[tid] = ev;
            __syncthreads();
            for (int o = 256; o > 0; o >>= 1) {
                if (tid < o) work[tid] = fmaxf(work[tid], work[tid + o]);
                __syncthreads();
            }
            float mx = work[0];
            __syncthreads();
            float p = expf(ev - mx);
            work[tid] = p;
            __syncthreads();
            for (int o = 256; o > 0; o >>= 1) {
                if (tid < o) work[tid] += work[tid + o];
                __syncthreads();
            }
            if (tid < NS) g_a[b * NS + tid] = p * (1.0f / work[0]);
        }
        gsync(tgt);

        // ==== P5 (dynamic, 192 jobs): gate-y GEMM (128) + context (64) ====
        {
            const int NJ = 192;
            unsigned* tick = &g_tick[2 * t + 1];
            if (tid == 0) *s_job = atomicAdd(tick, 1u);
            __syncthreads();
            int job = *s_job;
            while (job < NJ) {
                int nxt = 0;
                if (tid == 0) nxt = atomicAdd(tick, 1u);
                int jm = (job * 5) % NJ;
                if (jm < 128) {
                    int tile = jm >> 3, ge = jm & 7;
                    int gate = tile >> 2, tn = tile & 3;
                    const float* W = (gate == 0) ? Wi : (gate == 1) ? Wf
                                   : (gate == 2) ? Wg : Wo;
                    float acc[8][4] = {};
                    XYS xl;
                    gemm(xl, W, NU, tn * 256, ge * 64, 4, Xs, Ws, acc);
#pragma unroll
                    for (int i = 0; i < 8; i++)
                        *(float4*)(g_slabg + ((size_t)(ge * NB + r0 + i)) * 4096 +
                                   gate * NU + tn * 256 + c0) =
                            make_float4(acc[i][0], acc[i][1], acc[i][2], acc[i][3]);
                } else {
                    int b = jm - 128;
                    if (tid < NS) work[tid] = __ldcg(g_a + b * NS + tid);
                    __syncthreads();
                    const unsigned* hb = (const unsigned*)g_hb +
                                         (size_t)b * NS * (NU / 2) + tid;
                    float av0 = 0.f, av1 = 0.f;
#pragma unroll 8
                    for (int s2 = 0; s2 < NS; s2++) {
                        unsigned raw = __ldcg(hb + (size_t)s2 * (NU / 2));
                        float2 f2 = __bfloat1622float2(
                            *reinterpret_cast<const __nv_bfloat162*>(&raw));
                        float aw = work[s2];
                        av0 = fmaf(f2.x, aw, av0);
                        av1 = fmaf(f2.y, aw, av1);
                    }
                    *(float2*)(g_c + (size_t)b * NU + tid * 2) = make_float2(av0, av1);
                }
                if (tid == 0) *s_job = nxt;
                __syncthreads();
                job = *s_job;
            }
        }
        gsync(tgt);

        // ==== P6: reduce 24 gate slices + activations + s' (float4) ====
        for (int idx = gid; idx < NB * 256; idx += gth) {
            int b = idx >> 8, u = (idx & 255) << 2;
            const float* sb = g_slabg + (size_t)b * 4096 + u;
            float4 iv = *(const float4*)(bi + u);
            float4 fv = *(const float4*)(bf + u);
            float4 gv = *(const float4*)(bg + u);
            float4 ov = *(const float4*)(bo + u);
#pragma unroll
            for (int ge = 0; ge < 24; ge++) {
                const float* p = sb + (size_t)ge * NB * 4096;
                float4 a = __ldcg((const float4*)(p));
                float4 bq = __ldcg((const float4*)(p + NU));
                float4 cq = __ldcg((const float4*)(p + 2 * NU));
                float4 dq = __ldcg((const float4*)(p + 3 * NU));
                iv.x += a.x;  iv.y += a.y;  iv.z += a.z;  iv.w += a.w;
                fv.x += bq.x; fv.y += bq.y; fv.z += bq.z; fv.w += bq.w;
                gv.x += cq.x; gv.y += cq.y; gv.z += cq.z; gv.w += cq.w;
                ov.x += dq.x; ov.y += dq.y; ov.z += dq.z; ov.w += dq.w;
            }
            float4 cv = __ldcg((const float4*)(g_c + (size_t)b * NU + u));
            float4 sv;
            {
                float i0 = lut_eval(lsig, iv.x), f0 = lut_eval(lsig, fv.x);
                float gg = lut_eval(ltanh, gv.x), o0 = lut_eval(lsig, ov.x);
                sv.x = o0 * lut_eval(ltanh, fmaf(f0, cv.x, i0 * gg));
                i0 = lut_eval(lsig, iv.y); f0 = lut_eval(lsig, fv.y);
                gg = lut_eval(ltanh, gv.y); o0 = lut_eval(lsig, ov.y);
                sv.y = o0 * lut_eval(ltanh, fmaf(f0, cv.y, i0 * gg));
                i0 = lut_eval(lsig, iv.z); f0 = lut_eval(lsig, fv.z);
                gg = lut_eval(ltanh, gv.z); o0 = lut_eval(lsig, ov.z);
                sv.z = o0 * lut_eval(ltanh, fmaf(f0, cv.z, i0 * gg));
                i0 = lut_eval(lsig, iv.w); f0 = lut_eval(lsig, fv.w);
                gg = lut_eval(ltanh, gv.w); o0 = lut_eval(lsig, ov.w);
                sv.w = o0 * lut_eval(ltanh, fmaf(f0, cv.w, i0 * gg));
            }
            *(float4*)(g_s + (size_t)b * NU + u) = sv;
        }
        gsync(tgt);
    }
}

// ------------------------- launch --------------------------------------------------
extern "C" void kernel_launch(void* const* d_in, const int* in_sizes, int n_in,
                              void* d_out, int out_size) {
    (void)in_sizes; (void)n_in; (void)out_size;
    const float* h   = (const float*)d_in[0];
    const float* s0  = (const float*)d_in[1];
    const float* Wy1 = (const float*)d_in[2];
    const float* by1 = (const float*)d_in[3];
    const float* Wy2 = (const float*)d_in[4];
    const float* by2 = (const float*)d_in[5];
    const float* We1 = (const float*)d_in[6];
    const float* be1 = (const float*)d_in[7];
    const float* We2 = (const float*)d_in[8];
    const float* be2 = (const float*)d_in[9];
    const float* Wf  = (const float*)d_in[10];
    const float* bf  = (const float*)d_in[11];
    const float* Wi  = (const float*)d_in[12];
    const float* bi  = (const float*)d_in[13];
    const float* Wg  = (const float*)d_in[14];
    const float* bg  = (const float*)d_in[15];
    const float* Wo  = (const float*)d_in[16];
    const float* bo  = (const float*)d_in[17];
    float* out = (float*)d_out;

    int nsm = 148;
    cudaDeviceGetAttribute(&nsm, cudaDevAttrMultiProcessorCount, 0);

    const int PSMEM = 75296;
    static int smem_set = 0;
    if (!smem_set) {
        cudaFuncSetAttribute(k_all, cudaFuncAttributeMaxDynamicSharedMemorySize, PSMEM);
        smem_set = 1;
    }

    k_init<<<1, NTH>>>();
    k_all<<<nsm, NTH, PSMEM>>>(h, s0, Wy1, by1, Wy2, by2, We1, be1, We2, be2,
                               Wi, bi, Wf, bf, Wg, bg, Wo, bo, out);
}

// round 10
// speedup vs baseline: 1.5042x; 1.2565x over previous
#include <cuda_runtime.h>
#include <cuda_bf16.h>
#include <math.h>
#include <stdint.h>

#define NB 64
#define NS 256
#define NU 1024
#define NT 512
#define NTH 512
#define NBS (NB * NS)

__device__ __nv_bfloat16 g_h_h[NBS * NU], g_h_l[NBS * NU];
__device__ __nv_bfloat16 g_hpt[NBS * NU];                     // [u][b*256+s]
__device__ __nv_bfloat16 g_Wt1q_h[2048 * NU], g_Wt1q_l[2048 * NU];
__device__ __nv_bfloat16 g_Wy2t_h[NT * NU],   g_Wy2t_l[NT * NU];
__device__ __nv_bfloat16 g_Wgt_h[4096 * 1536], g_Wgt_l[4096 * 1536];
__device__ __nv_bfloat16 g_We1t_h[NU * NU],   g_We1t_l[NU * NU];
__device__ __nv_bfloat16 g_t1_h[NB * NU], g_t1_l[NB * NU];    // [b][u]
__device__ __nv_bfloat16 g_x_h[NB * 1536], g_x_l[NB * 1536];  // [b][y|s]
__device__ float g_q[NB * NU], g_c[NB * NU];
__device__ float g_e[NB * NS], g_a[NB * NS];
__device__ float g_gt[NB * 4096];
__device__ float2 g_lut_sig[2049], g_lut_tanh[2049];
__device__ unsigned g_cnt, g_phs;

#define O_LS 0
#define O_LT 16392
#define O_WK 32784
#define O_AH 44032
#define O_AL 52224
#define O_BH 60416
#define O_BL 68608
#define PSMEM 76800

#define SWZ(x) ((x) ^ (((x) >> 3) & 0x70))

__device__ __forceinline__ uint32_t smem_u32(const void* p) {
    uint32_t a;
    asm("{ .reg .u64 t; cvta.to.shared.u64 t, %1; cvt.u32.u64 %0, t; }" : "=r"(a) : "l"(p));
    return a;
}
__device__ __forceinline__ void ldsm4(uint32_t* r, uint32_t addr) {
    asm volatile("ldmatrix.sync.aligned.m8n8.x4.shared.b16 {%0,%1,%2,%3}, [%4];"
        : "=r"(r[0]), "=r"(r[1]), "=r"(r[2]), "=r"(r[3]) : "r"(addr));
}
__device__ __forceinline__ void hmma(float* d, const uint32_t* a, uint32_t b0, uint32_t b1) {
    asm volatile("mma.sync.aligned.m16n8k16.row.col.f32.bf16.bf16.f32 "
        "{%0,%1,%2,%3}, {%4,%5,%6,%7}, {%8,%9}, {%0,%1,%2,%3};"
        : "+f"(d[0]), "+f"(d[1]), "+f"(d[2]), "+f"(d[3])
        : "r"(a[0]), "r"(a[1]), "r"(a[2]), "r"(a[3]), "r"(b0), "r"(b1));
}
__device__ __forceinline__ float lut_eval(const float2* __restrict__ lut, float x) {
    float xc = fminf(fmaxf(x, -8.0f), 8.0f);
    float f  = fmaf(xc, 128.0f, 1024.0f);
    float m  = (f - 0.5f) + 12582912.0f;
    int  idx = __float_as_int(m) - 0x4B400000;
    float2 p = lut[idx];
    return fmaf(f - (m - 12582912.0f), p.y, p.x);
}
__device__ __forceinline__ void hilo(float v, __nv_bfloat16* hp, __nv_bfloat16* lp) {
    __nv_bfloat16 h = __float2bfloat16(v);
    *hp = h;
    *lp = __float2bfloat16(v - __bfloat162float(h));
}
__device__ __forceinline__ float bldg(const __nv_bfloat16* p) {
    unsigned short v = __ldcg((const unsigned short*)p);
    return __bfloat162float(*reinterpret_cast<__nv_bfloat16*>(&v));
}
__device__ __forceinline__ void gsync(unsigned& tgt) {
    tgt++;
    __syncthreads();
    if (threadIdx.x == 0) {
        __threadfence();
        if (atomicAdd(&g_cnt, 1u) == gridDim.x - 1) {
            g_cnt = 0; __threadfence(); atomicExch(&g_phs, tgt);
        } else {
            while (*(volatile unsigned*)&g_phs < tgt) { }
        }
    }
    __syncthreads();
}

__global__ void k_init() {
    int tid = threadIdx.x;
    if (tid == 0) { g_cnt = 0; g_phs = 0; }
    for (int i = tid; i < 2049; i += NTH) {
        float x0 = -8.0f + i * (1.0f / 128.0f), x1 = x0 + (1.0f / 128.0f);
        float sa = 1.0f / (1.0f + expf(-x0));
        float sb = (i == 2048) ? sa : 1.0f / (1.0f + expf(-x1));
        g_lut_sig[i] = make_float2(sa, sb - sa);
        float ta = tanhf(x0), tb = (i == 2048) ? ta : tanhf(x1);
        g_lut_tanh[i] = make_float2(ta, tb - ta);
    }
}

// D[64 x 64] = A[m0..+64][K](hi/lo) @ B[64][K](hi/lo)^T, 3-term hi/lo bf16 HMMA.
__device__ __forceinline__ void mma_job(
    char* dyn, uint32_t su,
    const __nv_bfloat16* aH, const __nv_bfloat16* aL, int lda,
    const __nv_bfloat16* bH, const __nv_bfloat16* bL, int ldb,
    int nch, float acc[2][4])
{
    const int tid = threadIdx.x, lane = tid & 31, warp = tid >> 5;
    const int wm = warp >> 2, wn = warp & 3;
    const int sr = tid >> 3, ss = tid & 7;
    const int arow = wm * 16 + (lane & 15), ablk = lane >> 4;
    const int brow = wn * 16 + (lane & 7) + ((lane >> 4) << 3), bblk = (lane >> 3) & 1;
    const uint32_t soff = SWZ((uint32_t)(sr * 128 + ss * 16));

    uint4 vah = *(const uint4*)(aH + (size_t)sr * lda + ss * 8);
    uint4 val = *(const uint4*)(aL + (size_t)sr * lda + ss * 8);
    uint4 vbh = __ldcg((const uint4*)(bH + (size_t)sr * ldb + ss * 8));
    uint4 vbl = __ldcg((const uint4*)(bL + (size_t)sr * ldb + ss * 8));

    for (int c = 0; c < nch; c++) {
        __syncthreads();
        *(uint4*)(dyn + O_AH + soff) = vah;
        *(uint4*)(dyn + O_AL + soff) = val;
        *(uint4*)(dyn + O_BH + soff) = vbh;
        *(uint4*)(dyn + O_BL + soff) = vbl;
        __syncthreads();
        if (c + 1 < nch) {
            int k = (c + 1) * 64 + ss * 8;
            vah = *(const uint4*)(aH + (size_t)sr * lda + k);
            val = *(const uint4*)(aL + (size_t)sr * lda + k);
            vbh = __ldcg((const uint4*)(bH + (size_t)sr * ldb + k));
            vbl = __ldcg((const uint4*)(bL + (size_t)sr * ldb + k));
        }
#pragma unroll
        for (int ks = 0; ks < 4; ks++) {
            uint32_t ao = SWZ((uint32_t)(arow * 128 + ks * 32 + ablk * 16));
            uint32_t bo = SWZ((uint32_t)(brow * 128 + ks * 32 + bblk * 16));
            uint32_t ah[4], al[4], bh[4], bl[4];
            ldsm4(ah, su + O_AH + ao);
            ldsm4(al, su + O_AL + ao);
            ldsm4(bh, su + O_BH + bo);
            ldsm4(bl, su + O_BL + bo);
            hmma(acc[0], ah, bh[0], bh[1]);
            hmma(acc[1], ah, bh[2], bh[3]);
            hmma(acc[0], ah, bl[0], bl[1]);
            hmma(acc[1], ah, bl[2], bl[3]);
            hmma(acc[0], al, bh[0], bh[1]);
            hmma(acc[1], al, bh[2], bh[3]);
        }
    }
}
// epilogue iteration: m_local(i) = wm*16 + (lane>>2) + i*8 ; n_local(na,j) = wn*16 + na*8 + (lane&3)*2 + j
#define EPI_LOOP(body) do {                                                     \
    const int _wm = (threadIdx.x >> 7), _wn = (threadIdx.x >> 5) & 3;           \
    const int _tq = (threadIdx.x & 31) >> 2, _tr = threadIdx.x & 3;             \
    _Pragma("unroll") for (int _i = 0; _i < 2; _i++) {                          \
        int ml = _wm * 16 + _tq + _i * 8;                                       \
        _Pragma("unroll") for (int _na = 0; _na < 2; _na++)                     \
        _Pragma("unroll") for (int _j = 0; _j < 2; _j++) {                      \
            int nl = _wn * 16 + _na * 8 + _tr * 2 + _j;                         \
            float v = acc[_na][_i * 2 + _j];                                    \
            body                                                                 \
        }                                                                        \
    }                                                                            \
} while (0)

__global__ __launch_bounds__(NTH, 1) void k_all(
    const float* __restrict__ h,  const float* __restrict__ s0,
    const float* __restrict__ Wy1, const float* __restrict__ by1,
    const float* __restrict__ Wy2, const float* __restrict__ by2,
    const float* __restrict__ We1, const float* __restrict__ be1,
    const float* __restrict__ We2, const float* __restrict__ be2,
    const float* __restrict__ Wi,  const float* __restrict__ bi,
    const float* __restrict__ Wf,  const float* __restrict__ bf,
    const float* __restrict__ Wg,  const float* __restrict__ bg,
    const float* __restrict__ Wo,  const float* __restrict__ bo,
    float* __restrict__ out)
{
    extern __shared__ char dyn[];
    float2* lsig  = (float2*)(dyn + O_LS);
    float2* ltanh = (float2*)(dyn + O_LT);
    float*  work  = (float*)(dyn + O_WK);
    const uint32_t su = smem_u32(dyn);
    const int tid = threadIdx.x, bid = blockIdx.x;
    const int gth = gridDim.x * NTH, gid = bid * NTH + tid;
    unsigned tgt = 0;

    for (int i = tid; i < 2049; i += NTH) { lsig[i] = g_lut_sig[i]; ltanh[i] = g_lut_tanh[i]; }
    __syncthreads();
    const float be2v = be2[0];

    // ---- A1: conversions + weight transposes (hi/lo) ----
    for (size_t i = gid; i < (size_t)NBS * NU; i += gth)
        hilo(__ldcs(h + i), g_h_h + i, g_h_l + i);
    for (int i = gid; i < 2048 * NU; i += gth) {
        int k = i >> 11, m = i & 2047;
        float v = (m < NU) ? Wy1[(size_t)k * NU + m] : We1[(size_t)(NU + k) * NU + (m - NU)];
        hilo(v, g_Wt1q_h + (size_t)m * NU + k, g_Wt1q_l + (size_t)m * NU + k);
    }
    for (int i = gid; i < NT * NU; i += gth) {
        int k = i >> 9, m = i & 511;
        hilo(Wy2[(size_t)k * NT + m], g_Wy2t_h + (size_t)m * NU + k, g_Wy2t_l + (size_t)m * NU + k);
    }
    for (int i = gid; i < 4096 * 1536; i += gth) {
        int k = i >> 12, m = i & 4095, gate = m >> 10, u = m & 1023;
        const float* W = (gate == 0) ? Wi : (gate == 1) ? Wf : (gate == 2) ? Wg : Wo;
        hilo(W[(size_t)k * NU + u], g_Wgt_h + (size_t)m * 1536 + k, g_Wgt_l + (size_t)m * 1536 + k);
    }
    for (int i = gid; i < NU * NU; i += gth) {
        int k = i >> 10, m = i & 1023;
        hilo(We1[(size_t)k * NU + m], g_We1t_h + (size_t)m * NU + k, g_We1t_l + (size_t)m * NU + k);
    }
    for (int i = gid; i < NB * NU; i += gth) {
        int b = i >> 10, u = i & 1023;
        hilo(s0[i], g_x_h + b * 1536 + 512 + u, g_x_l + b * 1536 + 512 + u);
    }
    gsync(tgt);

    // ---- A2: hproj = We1h^T @ h^T -> g_hpt[u][bs]  (4096 jobs) ----
    for (int j = bid; j < 4096; j += gridDim.x) {
        int m0 = (j >> 8) * 64, n0 = (j & 255) * 64;
        float acc[2][4] = {};
        mma_job(dyn, su, g_We1t_h + (size_t)m0 * NU, g_We1t_l + (size_t)m0 * NU, NU,
                g_h_h + (size_t)n0 * NU, g_h_l + (size_t)n0 * NU, NU, 16, acc);
        EPI_LOOP({
            g_hpt[(size_t)(m0 + ml) * NBS + n0 + nl] = __float2bfloat16(v);
        });
    }
    gsync(tgt);

    // =========================== scan ===========================
    for (int t = 0; t < NS; t++) {
        // P1: [t1|q] = Wt1q @ s  (32 jobs)
        for (int j = bid; j < 32; j += gridDim.x) {
            int m0 = j * 64;
            float acc[2][4] = {};
            mma_job(dyn, su, g_Wt1q_h + (size_t)m0 * NU, g_Wt1q_l + (size_t)m0 * NU, NU,
                    g_x_h + 512, g_x_l + 512, 1536, 16, acc);
            EPI_LOOP({
                int m = m0 + ml;
                if (m < NU) {
                    float tv = lut_eval(ltanh, v + by1[m]);
                    hilo(tv, g_t1_h + nl * NU + m, g_t1_l + nl * NU + m);
                } else {
                    g_q[nl * NU + (m - NU)] = v + be1[m - NU];
                }
            });
        }
        gsync(tgt);

        // P2: y (bids 0-7) + energies (bids 8-71)
        if (bid < 8) {
            int m0 = bid * 64;
            float acc[2][4] = {};
            mma_job(dyn, su, g_Wy2t_h + (size_t)m0 * NU, g_Wy2t_l + (size_t)m0 * NU, NU,
                    g_t1_h, g_t1_l, NU, 16, acc);
            EPI_LOOP({
                int m = m0 + ml;
                float vv = v + by2[m];
                out[((size_t)nl * NS + t) * NT + m] = vv;
                hilo(vv, g_x_h + nl * 1536 + m, g_x_l + nl * 1536 + m);
            });
        } else if (bid < 72) {
            int b = bid - 8;
            float2* swq = (float2*)work;
            for (int i = tid; i < NU; i += NTH)
                swq[i] = make_float2(__ldcg(g_q + b * NU + i), We2[i]);
            __syncthreads();
            int s = tid & 255, hf = tid >> 8;
            const __nv_bfloat16* hp = g_hpt + (size_t)(hf * 512) * NBS + b * NS + s;
            float av = 0.f;
#pragma unroll 8
            for (int u = 0; u < 512; u++) {
                float hv = __bfloat162float(hp[(size_t)u * NBS]);
                float2 qw = swq[hf * 512 + u];
                av = fmaf(lut_eval(lsig, hv + qw.x), qw.y, av);
            }
            float* ew = work + 2048;
            ew[tid] = av;
            __syncthreads();
            if (tid < 256) g_e[b * NS + tid] = lut_eval(lsig, ew[tid] + ew[tid + 256] + be2v);
        }
        gsync(tgt);

        // P3: softmax (bids 0-63)
        if (bid < NB) {
            float ev = (tid < NS) ? __ldcg(g_e + bid * NS + tid) : -1e30f;
            work[tid] = ev;
            __syncthreads();
            for (int o = 256; o > 0; o >>= 1) {
                if (tid < o) work[tid] = fmaxf(work[tid], work[tid + o]);
                __syncthreads();
            }
            float mx = work[0];
            __syncthreads();
            float p = expf(ev - mx);
            work[tid] = p;
            __syncthreads();
            for (int o = 256; o > 0; o >>= 1) {
                if (tid < o) work[tid] += work[tid + o];
                __syncthreads();
            }
            if (tid < NS) g_a[bid * NS + tid] = p * (1.0f / work[0]);
        }
        gsync(tgt);

        // P4: gates (bids 0-63, K=1536) + context (bids 64-127)
        if (bid < 64) {
            int m0 = bid * 64;
            float acc[2][4] = {};
            mma_job(dyn, su, g_Wgt_h + (size_t)m0 * 1536, g_Wgt_l + (size_t)m0 * 1536, 1536,
                    g_x_h, g_x_l, 1536, 24, acc);
            EPI_LOOP({
                g_gt[nl * 4096 + m0 + ml] = v;
            });
        } else if (bid < 128) {
            int b = bid - 64;
            if (tid < NS) work[tid] = __ldcg(g_a + b * NS + tid);
            __syncthreads();
#pragma unroll
            for (int uu = 0; uu < 2; uu++) {
                int u = uu * 512 + tid;
                const __nv_bfloat16* hb = g_h_h + (size_t)b * NS * NU + u;
                float a0 = 0.f, a1 = 0.f, a2 = 0.f, a3 = 0.f;
                for (int s2 = 0; s2 < NS; s2 += 4) {
                    a0 = fmaf(__bfloat162float(hb[(size_t)(s2 + 0) * NU]), work[s2 + 0], a0);
                    a1 = fmaf(__bfloat162float(hb[(size_t)(s2 + 1) * NU]), work[s2 + 1], a1);
                    a2 = fmaf(__bfloat162float(hb[(size_t)(s2 + 2) * NU]), work[s2 + 2], a2);
                    a3 = fmaf(__bfloat162float(hb[(size_t)(s2 + 3) * NU]), work[s2 + 3], a3);
                }
                g_c[b * NU + u] = (a0 + a1) + (a2 + a3);
            }
        }
        gsync(tgt);

        // P5: s' = o * tanh(f*c + i*g)
        for (int i = gid; i < NB * NU; i += gth) {
            int b = i >> 10, u = i & 1023;
            const float* gp = g_gt + b * 4096 + u;
            float iv = lut_eval(lsig,  __ldcg(gp)        + bi[u]);
            float fv = lut_eval(lsig,  __ldcg(gp + 1024) + bf[u]);
            float gv = lut_eval(ltanh, __ldcg(gp + 2048) + bg[u]);
            float ov = lut_eval(lsig,  __ldcg(gp + 3072) + bo[u]);
            float cv = __ldcg(g_c + i);
            float sv = ov * lut_eval(ltanh, fmaf(fv, cv, iv * gv));
            hilo(sv, g_x_h + b * 1536 + 512 + u, g_x_l + b * 1536 + 512 + u);
        }
        gsync(tgt);
    }
}

extern "C" void kernel_launch(void* const* d_in, const int* in_sizes, int n_in,
                              void* d_out, int out_size) {
    (void)in_sizes; (void)n_in; (void)out_size;
    const float* h   = (const float*)d_in[0];
    const float* s0  = (const float*)d_in[1];
    const float* Wy1 = (const float*)d_in[2];
    const float* by1 = (const float*)d_in[3];
    const float* Wy2 = (const float*)d_in[4];
    const float* by2 = (const float*)d_in[5];
    const float* We1 = (const float*)d_in[6];
    const float* be1 = (const float*)d_in[7];
    const float* We2 = (const float*)d_in[8];
    const float* be2 = (const float*)d_in[9];
    const float* Wf  = (const float*)d_in[10];
    const float* bf  = (const float*)d_in[11];
    const float* Wi  = (const float*)d_in[12];
    const float* bi  = (const float*)d_in[13];
    const float* Wg  = (const float*)d_in[14];
    const float* bg  = (const float*)d_in[15];
    const float* Wo  = (const float*)d_in[16];
    const float* bo  = (const float*)d_in[17];
    float* out = (float*)d_out;

    int nsm = 148;
    cudaDeviceGetAttribute(&nsm, cudaDevAttrMultiProcessorCount, 0);
    static int sset = 0;
    if (!sset) {
        cudaFuncSetAttribute(k_all, cudaFuncAttributeMaxDynamicSharedMemorySize, PSMEM);
        sset = 1;
    }
    k_init<<<1, NTH>>>();
    k_all<<<nsm, NTH, PSMEM>>>(h, s0, Wy1, by1, Wy2, by2, We1, be1, We2, be2,
                               Wi, bi, Wf, bf, Wg, bg, Wo, bo, out);
}

// round 11
// speedup vs baseline: 1.9390x; 1.2890x over previous
#include <cuda_runtime.h>
#include <cuda_bf16.h>
#include <math.h>
#include <stdint.h>

#define NB 64
#define NS 256
#define NU 1024
#define NT 512
#define NTH 512
#define NBS (NB * NS)

__device__ __nv_bfloat16 g_h_h[NBS * NU], g_h_l[NBS * NU];
__device__ __nv_bfloat16 g_hpt[NBS * NU];                     // [u][b*256+s]
__device__ __nv_bfloat16 g_Wt1q_h[2048 * NU], g_Wt1q_l[2048 * NU];
__device__ __nv_bfloat16 g_Wy2t_h[NT * NU],   g_Wy2t_l[NT * NU];
__device__ __nv_bfloat16 g_Wgt_h[4096 * 1536], g_Wgt_l[4096 * 1536];
__device__ __nv_bfloat16 g_We1t_h[NU * NU],   g_We1t_l[NU * NU];
__device__ __nv_bfloat16 g_t1_h[NB * NU], g_t1_l[NB * NU];    // [b][u]
__device__ __nv_bfloat16 g_x_h[NB * 1536], g_x_l[NB * 1536];  // [b][y|s]
__device__ float g_q[NB * NU], g_c[NB * NU];
__device__ float g_e[NB * NS];
__device__ float g_gt[NB * 4096];
__device__ float2 g_lut_sig[2049], g_lut_tanh[2049];
__device__ unsigned g_cnt, g_phs;

#define O_LS 0
#define O_LT 16392
#define O_WK 32784
#define O_AH 44032
#define O_AL 52224
#define O_BH 60416
#define O_BL 68608
#define PSMEM 76800

#define SWZ(x) ((x) ^ (((x) >> 3) & 0x70))

__device__ __forceinline__ uint32_t smem_u32(const void* p) {
    uint32_t a;
    asm("{ .reg .u64 t; cvta.to.shared.u64 t, %1; cvt.u32.u64 %0, t; }" : "=r"(a) : "l"(p));
    return a;
}
__device__ __forceinline__ void ldsm4(uint32_t* r, uint32_t addr) {
    asm volatile("ldmatrix.sync.aligned.m8n8.x4.shared.b16 {%0,%1,%2,%3}, [%4];"
        : "=r"(r[0]), "=r"(r[1]), "=r"(r[2]), "=r"(r[3]) : "r"(addr));
}
__device__ __forceinline__ void hmma(float* d, const uint32_t* a, uint32_t b0, uint32_t b1) {
    asm volatile("mma.sync.aligned.m16n8k16.row.col.f32.bf16.bf16.f32 "
        "{%0,%1,%2,%3}, {%4,%5,%6,%7}, {%8,%9}, {%0,%1,%2,%3};"
        : "+f"(d[0]), "+f"(d[1]), "+f"(d[2]), "+f"(d[3])
        : "r"(a[0]), "r"(a[1]), "r"(a[2]), "r"(a[3]), "r"(b0), "r"(b1));
}
__device__ __forceinline__ float lut_eval(const float2* __restrict__ lut, float x) {
    float xc = fminf(fmaxf(x, -8.0f), 8.0f);
    float f  = fmaf(xc, 128.0f, 1024.0f);
    float m  = (f - 0.5f) + 12582912.0f;
    int  idx = __float_as_int(m) - 0x4B400000;
    float2 p = lut[idx];
    return fmaf(f - (m - 12582912.0f), p.y, p.x);
}
__device__ __forceinline__ void hilo(float v, __nv_bfloat16* hp, __nv_bfloat16* lp) {
    __nv_bfloat16 h = __float2bfloat16(v);
    *hp = h;
    *lp = __float2bfloat16(v - __bfloat162float(h));
}
__device__ __forceinline__ void gsync(unsigned& tgt) {
    tgt++;
    __syncthreads();
    if (threadIdx.x == 0) {
        __threadfence();
        if (atomicAdd(&g_cnt, 1u) == gridDim.x - 1) {
            g_cnt = 0; __threadfence(); atomicExch(&g_phs, tgt);
        } else {
            while (*(volatile unsigned*)&g_phs < tgt) { }
        }
    }
    __syncthreads();
}

__global__ void k_init() {
    int tid = threadIdx.x;
    if (tid == 0) { g_cnt = 0; g_phs = 0; }
    for (int i = tid; i < 2049; i += NTH) {
        float x0 = -8.0f + i * (1.0f / 128.0f), x1 = x0 + (1.0f / 128.0f);
        float sa = 1.0f / (1.0f + expf(-x0));
        float sb = (i == 2048) ? sa : 1.0f / (1.0f + expf(-x1));
        g_lut_sig[i] = make_float2(sa, sb - sa);
        float ta = tanhf(x0), tb = (i == 2048) ? ta : tanhf(x1);
        g_lut_tanh[i] = make_float2(ta, tb - ta);
    }
}

// D[64 x 64] = A[m0..+64][K](hi/lo) @ B[64][K](hi/lo)^T, 3-term hi/lo bf16 HMMA.
__device__ __forceinline__ void mma_job(
    char* dyn, uint32_t su,
    const __nv_bfloat16* aH, const __nv_bfloat16* aL, int lda,
    const __nv_bfloat16* bH, const __nv_bfloat16* bL, int ldb,
    int nch, float acc[2][4])
{
    const int tid = threadIdx.x, lane = tid & 31, warp = tid >> 5;
    const int wm = warp >> 2, wn = warp & 3;
    const int sr = tid >> 3, ss = tid & 7;
    const int arow = wm * 16 + (lane & 15), ablk = lane >> 4;
    const int brow = wn * 16 + (lane & 7) + ((lane >> 4) << 3), bblk = (lane >> 3) & 1;
    const uint32_t soff = SWZ((uint32_t)(sr * 128 + ss * 16));

    uint4 vah = *(const uint4*)(aH + (size_t)sr * lda + ss * 8);
    uint4 val = *(const uint4*)(aL + (size_t)sr * lda + ss * 8);
    uint4 vbh = __ldcg((const uint4*)(bH + (size_t)sr * ldb + ss * 8));
    uint4 vbl = __ldcg((const uint4*)(bL + (size_t)sr * ldb + ss * 8));

    for (int c = 0; c < nch; c++) {
        __syncthreads();
        *(uint4*)(dyn + O_AH + soff) = vah;
        *(uint4*)(dyn + O_AL + soff) = val;
        *(uint4*)(dyn + O_BH + soff) = vbh;
        *(uint4*)(dyn + O_BL + soff) = vbl;
        __syncthreads();
        if (c + 1 < nch) {
            int k = (c + 1) * 64 + ss * 8;
            vah = *(const uint4*)(aH + (size_t)sr * lda + k);
            val = *(const uint4*)(aL + (size_t)sr * lda + k);
            vbh = __ldcg((const uint4*)(bH + (size_t)sr * ldb + k));
            vbl = __ldcg((const uint4*)(bL + (size_t)sr * ldb + k));
        }
#pragma unroll
        for (int ks = 0; ks < 4; ks++) {
            uint32_t ao = SWZ((uint32_t)(arow * 128 + ks * 32 + ablk * 16));
            uint32_t bo = SWZ((uint32_t)(brow * 128 + ks * 32 + bblk * 16));
            uint32_t ah[4], al[4], bh[4], bl[4];
            ldsm4(ah, su + O_AH + ao);
            ldsm4(al, su + O_AL + ao);
            ldsm4(bh, su + O_BH + bo);
            ldsm4(bl, su + O_BL + bo);
            hmma(acc[0], ah, bh[0], bh[1]);
            hmma(acc[1], ah, bh[2], bh[3]);
            hmma(acc[0], ah, bl[0], bl[1]);
            hmma(acc[1], ah, bl[2], bl[3]);
            hmma(acc[0], al, bh[0], bh[1]);
            hmma(acc[1], al, bh[2], bh[3]);
        }
    }
}
#define EPI_LOOP(body) do {                                                     \
    const int _wm = (threadIdx.x >> 7), _wn = (threadIdx.x >> 5) & 3;           \
    const int _tq = (threadIdx.x & 31) >> 2, _tr = threadIdx.x & 3;             \
    _Pragma("unroll") for (int _i = 0; _i < 2; _i++) {                          \
        int ml = _wm * 16 + _tq + _i * 8;                                       \
        _Pragma("unroll") for (int _na = 0; _na < 2; _na++)                     \
        _Pragma("unroll") for (int _j = 0; _j < 2; _j++) {                      \
            int nl = _wn * 16 + _na * 8 + _tr * 2 + _j;                         \
            float v = acc[_na][_i * 2 + _j];                                    \
            body                                                                 \
        }                                                                        \
    }                                                                            \
} while (0)

__global__ __launch_bounds__(NTH, 1) void k_all(
    const float* __restrict__ h,  const float* __restrict__ s0,
    const float* __restrict__ Wy1, const float* __restrict__ by1,
    const float* __restrict__ Wy2, const float* __restrict__ by2,
    const float* __restrict__ We1, const float* __restrict__ be1,
    const float* __restrict__ We2, const float* __restrict__ be2,
    const float* __restrict__ Wi,  const float* __restrict__ bi,
    const float* __restrict__ Wf,  const float* __restrict__ bf,
    const float* __restrict__ Wg,  const float* __restrict__ bg,
    const float* __restrict__ Wo,  const float* __restrict__ bo,
    float* __restrict__ out)
{
    extern __shared__ char dyn[];
    float2* lsig  = (float2*)(dyn + O_LS);
    float2* ltanh = (float2*)(dyn + O_LT);
    float*  work  = (float*)(dyn + O_WK);
    const uint32_t su = smem_u32(dyn);
    const int tid = threadIdx.x, bid = blockIdx.x;
    const int gth = gridDim.x * NTH, gid = bid * NTH + tid;
    unsigned tgt = 0;

    for (int i = tid; i < 2049; i += NTH) { lsig[i] = g_lut_sig[i]; ltanh[i] = g_lut_tanh[i]; }
    __syncthreads();
    const float be2v = be2[0];

    // ---- A1: conversions + weight transposes (hi/lo) ----
    for (size_t i = gid; i < (size_t)NBS * NU; i += gth)
        hilo(__ldcs(h + i), g_h_h + i, g_h_l + i);
    for (int i = gid; i < 2048 * NU; i += gth) {
        int k = i >> 11, m = i & 2047;
        float v = (m < NU) ? Wy1[(size_t)k * NU + m] : We1[(size_t)(NU + k) * NU + (m - NU)];
        hilo(v, g_Wt1q_h + (size_t)m * NU + k, g_Wt1q_l + (size_t)m * NU + k);
    }
    for (int i = gid; i < NT * NU; i += gth) {
        int k = i >> 9, m = i & 511;
        hilo(Wy2[(size_t)k * NT + m], g_Wy2t_h + (size_t)m * NU + k, g_Wy2t_l + (size_t)m * NU + k);
    }
    for (int i = gid; i < 4096 * 1536; i += gth) {
        int k = i >> 12, m = i & 4095, gate = m >> 10, u = m & 1023;
        const float* W = (gate == 0) ? Wi : (gate == 1) ? Wf : (gate == 2) ? Wg : Wo;
        hilo(W[(size_t)k * NU + u], g_Wgt_h + (size_t)m * 1536 + k, g_Wgt_l + (size_t)m * 1536 + k);
    }
    for (int i = gid; i < NU * NU; i += gth) {
        int k = i >> 10, m = i & 1023;
        hilo(We1[(size_t)k * NU + m], g_We1t_h + (size_t)m * NU + k, g_We1t_l + (size_t)m * NU + k);
    }
    for (int i = gid; i < NB * NU; i += gth) {
        int b = i >> 10, u = i & 1023;
        hilo(s0[i], g_x_h + b * 1536 + 512 + u, g_x_l + b * 1536 + 512 + u);
    }
    gsync(tgt);

    // ---- A2: hproj = We1h^T @ h^T -> g_hpt[u][bs]  (4096 jobs) ----
    for (int j = bid; j < 4096; j += gridDim.x) {
        int m0 = (j >> 8) * 64, n0 = (j & 255) * 64;
        float acc[2][4] = {};
        mma_job(dyn, su, g_We1t_h + (size_t)m0 * NU, g_We1t_l + (size_t)m0 * NU, NU,
                g_h_h + (size_t)n0 * NU, g_h_l + (size_t)n0 * NU, NU, 16, acc);
        EPI_LOOP({
            g_hpt[(size_t)(m0 + ml) * NBS + n0 + nl] = __float2bfloat16(v);
        });
    }
    gsync(tgt);

    // =========================== scan (4 barriers/step) ===========================
    for (int t = 0; t < NS; t++) {
        // P1: [t1|q] = Wt1q @ s (bids 0-31); zero g_e (bids 32-63)
        if (bid < 32) {
            int m0 = bid * 64;
            float acc[2][4] = {};
            mma_job(dyn, su, g_Wt1q_h + (size_t)m0 * NU, g_Wt1q_l + (size_t)m0 * NU, NU,
                    g_x_h + 512, g_x_l + 512, 1536, 16, acc);
            EPI_LOOP({
                int m = m0 + ml;
                if (m < NU) {
                    float tv = lut_eval(ltanh, v + by1[m]);
                    hilo(tv, g_t1_h + nl * NU + m, g_t1_l + nl * NU + m);
                } else {
                    g_q[nl * NU + (m - NU)] = v + be1[m - NU];
                }
            });
        } else if (bid < 64) {
            g_e[(bid - 32) * NTH + tid] = 0.f;
        }
        gsync(tgt);

        // P2: y (bids 0-7) + energy partial dots (bids 8-135, b x u-half, atomicAdd)
        if (bid < 8) {
            int m0 = bid * 64;
            float acc[2][4] = {};
            mma_job(dyn, su, g_Wy2t_h + (size_t)m0 * NU, g_Wy2t_l + (size_t)m0 * NU, NU,
                    g_t1_h, g_t1_l, NU, 16, acc);
            EPI_LOOP({
                int m = m0 + ml;
                float vv = v + by2[m];
                out[((size_t)nl * NS + t) * NT + m] = vv;
                hilo(vv, g_x_h + nl * 1536 + m, g_x_l + nl * 1536 + m);
            });
        } else if (bid < 136) {
            int e = bid - 8, b = e >> 1, uh = e & 1;
            float2* swq = (float2*)work;            // (q, We2) for this u-half
            {
                int u = uh * 512 + tid;
                swq[tid] = make_float2(__ldcg(g_q + b * NU + u), We2[u]);
            }
            __syncthreads();
            int s = tid & 255, up = tid >> 8;
            const unsigned short* hp = (const unsigned short*)g_hpt +
                                       (size_t)(uh * 512 + up * 256) * NBS + b * NS + s;
            float av = 0.f;
#pragma unroll 8
            for (int u = 0; u < 256; u++) {
                unsigned short raw = __ldcg(hp + (size_t)u * NBS);
                float hv = __int_as_float((int)((unsigned)raw << 16));
                float2 qw = swq[up * 256 + u];
                av = fmaf(lut_eval(lsig, hv + qw.x), qw.y, av);
            }
            float* ew = work + 1024;
            ew[tid] = av;
            __syncthreads();
            if (tid < 256) atomicAdd(&g_e[b * NS + tid], ew[tid] + ew[tid + 256]);
        }
        gsync(tgt);

        // P4: gates (bids 0-63) + context w/ local softmax (bids 64-127)
        if (bid < 64) {
            int m0 = bid * 64;
            float acc[2][4] = {};
            mma_job(dyn, su, g_Wgt_h + (size_t)m0 * 1536, g_Wgt_l + (size_t)m0 * 1536, 1536,
                    g_x_h, g_x_l, 1536, 24, acc);
            EPI_LOOP({
                g_gt[nl * 4096 + m0 + ml] = v;
            });
        } else if (bid < 128) {
            int b = bid - 64;
            float ev = (tid < NS) ? lut_eval(lsig, __ldcg(g_e + b * NS + tid) + be2v) : -1e30f;
            work[tid] = ev;
            __syncthreads();
            for (int o = 256; o > 0; o >>= 1) {
                if (tid < o) work[tid] = fmaxf(work[tid], work[tid + o]);
                __syncthreads();
            }
            float mx = work[0];
            __syncthreads();
            float p = expf(ev - mx);
            work[tid] = p;
            __syncthreads();
            for (int o = 256; o > 0; o >>= 1) {
                if (tid < o) work[tid] += work[tid + o];
                __syncthreads();
            }
            float rinv = 1.0f / work[0];
            float* aw = work + 512;
            if (tid < NS) aw[tid] = p * rinv;
            __syncthreads();
            const unsigned* hb = (const unsigned*)(g_h_h + (size_t)b * NS * NU) + tid;
            float a0 = 0.f, a1 = 0.f, a2 = 0.f, a3 = 0.f;
#pragma unroll 4
            for (int s2 = 0; s2 < NS; s2 += 2) {
                unsigned r0 = __ldcg(hb + (size_t)(s2 + 0) * (NU / 2));
                unsigned r1 = __ldcg(hb + (size_t)(s2 + 1) * (NU / 2));
                float w0 = aw[s2], w1 = aw[s2 + 1];
                a0 = fmaf(__int_as_float((int)(r0 << 16)), w0, a0);
                a1 = fmaf(__int_as_float((int)(r0 & 0xFFFF0000u)), w0, a1);
                a2 = fmaf(__int_as_float((int)(r1 << 16)), w1, a2);
                a3 = fmaf(__int_as_float((int)(r1 & 0xFFFF0000u)), w1, a3);
            }
            g_c[b * NU + 2 * tid]     = a0 + a2;
            g_c[b * NU + 2 * tid + 1] = a1 + a3;
        }
        gsync(tgt);

        // P5: s' = o * tanh(f*c + i*g)
        for (int i = gid; i < NB * NU; i += gth) {
            int b = i >> 10, u = i & 1023;
            const float* gp = g_gt + b * 4096 + u;
            float iv = lut_eval(lsig,  __ldcg(gp)        + bi[u]);
            float fv = lut_eval(lsig,  __ldcg(gp + 1024) + bf[u]);
            float gv = lut_eval(ltanh, __ldcg(gp + 2048) + bg[u]);
            float ov = lut_eval(lsig,  __ldcg(gp + 3072) + bo[u]);
            float cv = __ldcg(g_c + i);
            float sv = ov * lut_eval(ltanh, fmaf(fv, cv, iv * gv));
            hilo(sv, g_x_h + b * 1536 + 512 + u, g_x_l + b * 1536 + 512 + u);
        }
        gsync(tgt);
    }
}

extern "C" void kernel_launch(void* const* d_in, const int* in_sizes, int n_in,
                              void* d_out, int out_size) {
    (void)in_sizes; (void)n_in; (void)out_size;
    const float* h   = (const float*)d_in[0];
    const float* s0  = (const float*)d_in[1];
    const float* Wy1 = (const float*)d_in[2];
    const float* by1 = (const float*)d_in[3];
    const float* Wy2 = (const float*)d_in[4];
    const float* by2 = (const float*)d_in[5];
    const float* We1 = (const float*)d_in[6];
    const float* be1 = (const float*)d_in[7];
    const float* We2 = (const float*)d_in[8];
    const float* be2 = (const float*)d_in[9];
    const float* Wf  = (const float*)d_in[10];
    const float* bf  = (const float*)d_in[11];
    const float* Wi  = (const float*)d_in[12];
    const float* bi  = (const float*)d_in[13];
    const float* Wg  = (const float*)d_in[14];
    const float* bg  = (const float*)d_in[15];
    const float* Wo  = (const float*)d_in[16];
    const float* bo  = (const float*)d_in[17];
    float* out = (float*)d_out;

    int nsm = 148;
    cudaDeviceGetAttribute(&nsm, cudaDevAttrMultiProcessorCount, 0);
    static int sset = 0;
    if (!sset) {
        cudaFuncSetAttribute(k_all, cudaFuncAttributeMaxDynamicSharedMemorySize, PSMEM);
        sset = 1;
    }
    k_init<<<1, NTH>>>();
    k_all<<<nsm, NTH, PSMEM>>>(h, s0, Wy1, by1, Wy2, by2, We1, be1, We2, be2,
                               Wi, bi, Wf, bf, Wg, bg, Wo, bo, out);
}